// round 6
// baseline (speedup 1.0000x reference)
#include <cuda_runtime.h>
#include <cuda_bf16.h>

#define B_  2
#define L_  2048
#define E_  512
#define H_  8
#define D_  64
#define NC  65
#define KP  240        // split-K layout: [Chi 80][Clo 80][Chi 80] x [Bhi;Bhi;Blo]
#define BH  (B_*H_)

typedef unsigned int uint;

// -------- scratch --------
__device__ float g_C[(size_t)BH * L_ * NC];
__device__ __nv_bfloat16 gCs[(size_t)BH * L_ * KP];   // 15.7 MB
__device__ __nv_bfloat16 gBs[KP * L_];                // 0.98 MB
__device__ float g_Zp[16 * BH * L_];                  // per-t-tile partial row sums
__device__ float g_invZ[BH * L_];
__device__ float g_P[(size_t)BH * L_ * L_];           // 268 MB
__device__ float g_Opart[2 * BH * D_ * L_];           // 16 MB  [z][bh][d][l]

__device__ __forceinline__ void mma_bf16(float4& c,
                                         uint a0, uint a1, uint a2, uint a3,
                                         uint b0, uint b1) {
    asm volatile(
        "mma.sync.aligned.m16n8k16.row.col.f32.bf16.bf16.f32 "
        "{%0,%1,%2,%3}, {%4,%5,%6,%7}, {%8,%9}, {%0,%1,%2,%3};"
        : "+f"(c.x), "+f"(c.y), "+f"(c.z), "+f"(c.w)
        : "r"(a0), "r"(a1), "r"(a2), "r"(a3), "r"(b0), "r"(b1));
}

// ============ K0a: split basis table  gBs[240][2048] ============
__global__ void bsplit_kernel() {
    int idx = blockIdx.x * blockDim.x + threadIdx.x;
    if (idx >= KP * L_) return;
    int t = idx % L_, r = idx / L_;
    int k = r % 80, part = r / 80;       // part 0,1 -> hi ; 2 -> lo
    float v = 0.f;
    if (k == 0) v = 1.0f;
    else if (k < NC) {
        int f = (k + 1) >> 1;
        int ph = (f * t) & (L_ - 1);
        float s, c;
        sincospif((float)ph * (1.0f / 1024.0f), &s, &c);
        v = (k & 1) ? c : s;
    }
    __nv_bfloat16 hv = __float2bfloat16(v);
    if (part == 2) hv = __float2bfloat16(v - __bfloat162float(hv));
    gBs[idx] = hv;
}

// ============ K1: 64-pt DFTs -> coeffs (fp32), head-mean subtracted ============
__global__ __launch_bounds__(288) void coeff_kernel(const float* __restrict__ q,
                                                    const float* __restrict__ kin) {
    int bs = blockIdx.x;
    int b  = bs >> 11;
    int s  = bs & (L_ - 1);

    __shared__ float sq[E_], sk[E_];
    __shared__ float twc[64], tws[64];
    __shared__ float A[H_][NC];

    int tid = threadIdx.x;
    for (int i = tid; i < E_; i += blockDim.x) {
        sq[i] = q[(size_t)bs * E_ + i];
        sk[i] = kin[(size_t)bs * E_ + i];
    }
    if (tid < 64) {
        float ss, cc;
        sincospif((float)tid * (1.0f / 32.0f), &ss, &cc);
        twc[tid] = cc; tws[tid] = ss;
    }
    __syncthreads();

    if (tid < H_ * 33) {
        int h = tid / 33, f = tid % 33;
        const float* qh = sq + h * D_;
        const float* kh = sk + h * D_;
        float Qr = 0.f, Qi = 0.f, Kr = 0.f, Ki = 0.f;
#pragma unroll 8
        for (int j = 0; j < 64; j++) {
            int m = (f * j) & 63;
            float c = twc[m], sn = tws[m];
            float qq = qh[j], kk2 = kh[j];
            Qr = fmaf(qq, c, Qr);  Qi = fmaf(-qq, sn, Qi);
            Kr = fmaf(kk2, c, Kr); Ki = fmaf(-kk2, sn, Ki);
        }
        float Xr = Qr * Kr + Qi * Ki;
        float Xi = Qi * Kr - Qr * Ki;
        if (f == 0) {
            A[h][0] = Xr * (1.0f / 2048.0f);
        } else {
            A[h][2 * f - 1] =  Xr * (1.0f / 1024.0f);
            A[h][2 * f]     = -Xi * (1.0f / 1024.0f);
        }
    }
    __syncthreads();

    for (int idx = tid; idx < H_ * NC; idx += blockDim.x) {
        int h = idx / NC, kk = idx % NC;
        float m = 0.f;
#pragma unroll
        for (int hh = 0; hh < H_; hh++) m += A[hh][kk];
        m *= (1.0f / H_);
        g_C[((size_t)(b * H_ + h) * L_ + s) * NC + kk] = A[h][kk] - m;
    }
}

// ============ K1b: split coeffs  gCs[bh][s][240] ============
__global__ void csplit_kernel() {
    size_t idx = (size_t)blockIdx.x * blockDim.x + threadIdx.x;
    if (idx >= (size_t)BH * L_ * KP) return;
    int c = (int)(idx % KP);
    size_t bs = idx / KP;
    int k = c % 80, part = c / 80;       // part 0,2 -> hi ; 1 -> lo
    float x = (k < NC) ? g_C[bs * NC + k] : 0.f;
    __nv_bfloat16 hv = __float2bfloat16(x);
    if (part == 1) hv = __float2bfloat16(x - __bfloat162float(hv));
    gCs[idx] = hv;
}

// ============ K2: tensor corr GEMM + exp -> P, partial rowsum ============
// grid (16 ttiles, 16 stiles, 16 bh), 256 thr, CTA tile 128x128, K=240.
#define PCHA 56
#define PCHB 60
__global__ __launch_bounds__(256) void z_mma_kernel() {
    int bh    = blockIdx.z;
    int sbase = blockIdx.y * 128;
    int tbase = blockIdx.x * 128;

    __shared__ __align__(16) __nv_bfloat16 As[128 * PCHA];   // [s][k]
    __shared__ __align__(16) __nv_bfloat16 Bts[128 * PCHB];  // [t][k]
    __shared__ float zsh[128];

    int tid = threadIdx.x;
    int lane = tid & 31, wid = tid >> 5;
    int g = lane >> 2, tg = lane & 3;
    int wm = wid >> 2, wn = wid & 3;       // warp tile m64 n32

    if (tid < 128) zsh[tid] = 0.f;

    float4 acc[4][4];
#pragma unroll
    for (int i = 0; i < 4; i++)
#pragma unroll
        for (int j = 0; j < 4; j++) acc[i][j] = make_float4(0.f, 0.f, 0.f, 0.f);

    const size_t abase = ((size_t)bh * L_ + sbase) * KP;

    for (int ch = 0; ch < 5; ch++) {               // 5 chunks of K=48
        __syncthreads();
        {   // stage A: 128 rows x 48 k
            int row = tid >> 1, part = tid & 1;
#pragma unroll
            for (int j = 0; j < 3; j++) {
                int colv = part * 3 + j;
                uint4 w = *(const uint4*)(gCs + abase + (size_t)row * KP + ch * 48 + colv * 8);
                *(uint4*)(As + row * PCHA + colv * 8) = w;
            }
        }
        {   // stage B transposed: [t][k]
            int kr0 = tid >> 4, tq = tid & 15;
#pragma unroll
            for (int j = 0; j < 3; j++) {
                int kr = kr0 + 16 * j;
                uint4 w = *(const uint4*)(gBs + (size_t)(ch * 48 + kr) * L_ + tbase + tq * 8);
                __nv_bfloat16 tmp[8];
                *(uint4*)tmp = w;
#pragma unroll
                for (int u = 0; u < 8; u++)
                    Bts[(tq * 8 + u) * PCHB + kr] = tmp[u];
            }
        }
        __syncthreads();

#pragma unroll
        for (int ks = 0; ks < 3; ks++) {
            int kofs = ks * 16;
            uint a[4][4], bb[4][2];
#pragma unroll
            for (int mi = 0; mi < 4; mi++) {
                int r0 = (wm * 64 + mi * 16 + g) * PCHA + kofs + 2 * tg;
                a[mi][0] = *(const uint*)&As[r0];
                a[mi][1] = *(const uint*)&As[r0 + 8 * PCHA];
                a[mi][2] = *(const uint*)&As[r0 + 8];
                a[mi][3] = *(const uint*)&As[r0 + 8 * PCHA + 8];
            }
#pragma unroll
            for (int ni = 0; ni < 4; ni++) {
                int c0 = (wn * 32 + ni * 8 + g) * PCHB + kofs + 2 * tg;
                bb[ni][0] = *(const uint*)&Bts[c0];
                bb[ni][1] = *(const uint*)&Bts[c0 + 8];
            }
#pragma unroll
            for (int mi = 0; mi < 4; mi++)
#pragma unroll
                for (int ni = 0; ni < 4; ni++)
                    mma_bf16(acc[mi][ni], a[mi][0], a[mi][1], a[mi][2], a[mi][3],
                             bb[ni][0], bb[ni][1]);
        }
    }

    // epilogue: exp, store P, row-sum partials
    const size_t Pbase = (size_t)bh * L_ * L_;
    float zl[4][2];
#pragma unroll
    for (int mi = 0; mi < 4; mi++) { zl[mi][0] = 0.f; zl[mi][1] = 0.f; }
#pragma unroll
    for (int mi = 0; mi < 4; mi++) {
        int r0 = sbase + wm * 64 + mi * 16 + g;
#pragma unroll
        for (int ni = 0; ni < 4; ni++) {
            int tc = tbase + wn * 32 + ni * 8 + 2 * tg;
            float4 c = acc[mi][ni];
            float e0 = __expf(c.x), e1 = __expf(c.y);
            float e2 = __expf(c.z), e3 = __expf(c.w);
            zl[mi][0] += e0 + e1;
            zl[mi][1] += e2 + e3;
            *(float2*)&g_P[Pbase + (size_t)r0 * L_ + tc]       = make_float2(e0, e1);
            *(float2*)&g_P[Pbase + (size_t)(r0 + 8) * L_ + tc] = make_float2(e2, e3);
        }
    }
#pragma unroll
    for (int mi = 0; mi < 4; mi++)
#pragma unroll
        for (int hh = 0; hh < 2; hh++) {
            float v = zl[mi][hh];
            v += __shfl_xor_sync(0xffffffffu, v, 1);
            v += __shfl_xor_sync(0xffffffffu, v, 2);
            if (tg == 0) atomicAdd(&zsh[wm * 64 + mi * 16 + g + hh * 8], v);
        }
    __syncthreads();
    if (tid < 128)
        g_Zp[((size_t)blockIdx.x * BH + bh) * L_ + sbase + tid] = zsh[tid];
}

// ============ K2b: combine 16 t-tile partials -> invZ ============
__global__ void zcombine_kernel() {
    int i = blockIdx.x * blockDim.x + threadIdx.x;
    if (i >= BH * L_) return;
    float z = 0.f;
#pragma unroll
    for (int tt = 0; tt < 16; tt++) z += g_Zp[(size_t)tt * (BH * L_) + i];
    g_invZ[i] = 1.0f / z;
}

// ============ K3: tensor out GEMM (split-bf16 of P and V on the fly) ============
// grid (16 ltiles, 16 bh, 2 s-halves), 256 thr, CTA tile 128(l) x 64(d).
#define PC3 40
__global__ __launch_bounds__(256) void out_mma_kernel(const float* __restrict__ values) {
    int bh = blockIdx.y;
    int b  = bh >> 3, h = bh & 7;
    int lbase = blockIdx.x * 128;
    int zhalf = blockIdx.z;

    __shared__ __align__(16) char smemraw[33280];   // max(staging 30720, osb 33280)
    __nv_bfloat16* Ahi = (__nv_bfloat16*)smemraw;           // [128 l][PC3 s]
    __nv_bfloat16* Alo = Ahi + 128 * PC3;
    __nv_bfloat16* Vhi = Alo + 128 * PC3;                   // [64 d][PC3 s]
    __nv_bfloat16* Vlo = Vhi + 64 * PC3;
    float* osb = (float*)smemraw;                            // [128 l][65] (after loop)

    int tid = threadIdx.x;
    int lane = tid & 31, wid = tid >> 5;
    int g = lane >> 2, tg = lane & 3;
    int wm = wid >> 1, wn = wid & 1;      // warp tile m32 n32

    float4 acc[2][4];
#pragma unroll
    for (int i = 0; i < 2; i++)
#pragma unroll
        for (int j = 0; j < 4; j++) acc[i][j] = make_float4(0.f, 0.f, 0.f, 0.f);

    const size_t Pbase = (size_t)bh * L_ * L_;
    const float* vptr = values + (size_t)b * L_ * E_ + h * D_;

    for (int sch = 0; sch < 32; sch++) {             // chunks of 32 s
        int sbase = zhalf * 1024 + sch * 32;
        __syncthreads();
        {   // stage A: P[s][l] tile -> Ahi/Alo[l][s], pre-multiplied by invZ
            int sc = tid >> 3, lq = tid & 7;
            float iz = g_invZ[bh * L_ + sbase + sc];
#pragma unroll
            for (int j = 0; j < 4; j++) {
                int l4 = lq + 8 * j;
                float4 p = *(const float4*)&g_P[Pbase + (size_t)(sbase + sc) * L_ + lbase + l4 * 4];
                float pv[4] = {p.x * iz, p.y * iz, p.z * iz, p.w * iz};
#pragma unroll
                for (int e = 0; e < 4; e++) {
                    int l = l4 * 4 + e;
                    __nv_bfloat16 hi = __float2bfloat16(pv[e]);
                    __nv_bfloat16 lo = __float2bfloat16(pv[e] - __bfloat162float(hi));
                    Ahi[l * PC3 + sc] = hi;
                    Alo[l * PC3 + sc] = lo;
                }
            }
        }
        {   // stage V: v[s][d] -> Vhi/Vlo[d][s]
            int sc = tid >> 3, dq = tid & 7;
#pragma unroll
            for (int j = 0; j < 2; j++) {
                int d4 = dq + 8 * j;
                float4 v4 = *(const float4*)&vptr[(size_t)(sbase + sc) * E_ + d4 * 4];
                float pv[4] = {v4.x, v4.y, v4.z, v4.w};
#pragma unroll
                for (int e = 0; e < 4; e++) {
                    int d = d4 * 4 + e;
                    __nv_bfloat16 hi = __float2bfloat16(pv[e]);
                    __nv_bfloat16 lo = __float2bfloat16(pv[e] - __bfloat162float(hi));
                    Vhi[d * PC3 + sc] = hi;
                    Vlo[d * PC3 + sc] = lo;
                }
            }
        }
        __syncthreads();

#pragma unroll
        for (int ks = 0; ks < 2; ks++) {
            int kofs = ks * 16;
            uint ah[2][4], al[2][4], vh[4][2], vl[4][2];
#pragma unroll
            for (int mi = 0; mi < 2; mi++) {
                int r0 = (wm * 32 + mi * 16 + g) * PC3 + kofs + 2 * tg;
                ah[mi][0] = *(const uint*)&Ahi[r0];
                ah[mi][1] = *(const uint*)&Ahi[r0 + 8 * PC3];
                ah[mi][2] = *(const uint*)&Ahi[r0 + 8];
                ah[mi][3] = *(const uint*)&Ahi[r0 + 8 * PC3 + 8];
                al[mi][0] = *(const uint*)&Alo[r0];
                al[mi][1] = *(const uint*)&Alo[r0 + 8 * PC3];
                al[mi][2] = *(const uint*)&Alo[r0 + 8];
                al[mi][3] = *(const uint*)&Alo[r0 + 8 * PC3 + 8];
            }
#pragma unroll
            for (int ni = 0; ni < 4; ni++) {
                int c0 = (wn * 32 + ni * 8 + g) * PC3 + kofs + 2 * tg;
                vh[ni][0] = *(const uint*)&Vhi[c0];
                vh[ni][1] = *(const uint*)&Vhi[c0 + 8];
                vl[ni][0] = *(const uint*)&Vlo[c0];
                vl[ni][1] = *(const uint*)&Vlo[c0 + 8];
            }
#pragma unroll
            for (int mi = 0; mi < 2; mi++)
#pragma unroll
                for (int ni = 0; ni < 4; ni++) {
                    mma_bf16(acc[mi][ni], ah[mi][0], ah[mi][1], ah[mi][2], ah[mi][3],
                             vh[ni][0], vh[ni][1]);
                    mma_bf16(acc[mi][ni], al[mi][0], al[mi][1], al[mi][2], al[mi][3],
                             vh[ni][0], vh[ni][1]);
                    mma_bf16(acc[mi][ni], ah[mi][0], ah[mi][1], ah[mi][2], ah[mi][3],
                             vl[ni][0], vl[ni][1]);
                }
        }
    }

    __syncthreads();
    // accums -> osb[l][65]
#pragma unroll
    for (int mi = 0; mi < 2; mi++) {
        int l0 = wm * 32 + mi * 16 + g;
#pragma unroll
        for (int ni = 0; ni < 4; ni++) {
            int d0 = wn * 32 + ni * 8 + 2 * tg;
            float4 c = acc[mi][ni];
            osb[l0 * 65 + d0]           = c.x;
            osb[l0 * 65 + d0 + 1]       = c.y;
            osb[(l0 + 8) * 65 + d0]     = c.z;
            osb[(l0 + 8) * 65 + d0 + 1] = c.w;
        }
    }
    __syncthreads();
    {   // coalesced global write of partial [d][l]
        int dq = tid >> 2, lq = tid & 3;
        float* op = &g_Opart[(((size_t)zhalf * BH + bh) * D_ + dq) * L_ + lbase];
#pragma unroll
        for (int j = 0; j < 8; j++) {
            int l4 = lq + 4 * j;
            float4 w;
            w.x = osb[(l4 * 4 + 0) * 65 + dq];
            w.y = osb[(l4 * 4 + 1) * 65 + dq];
            w.z = osb[(l4 * 4 + 2) * 65 + dq];
            w.w = osb[(l4 * 4 + 3) * 65 + dq];
            *(float4*)&op[l4 * 4] = w;
        }
    }
}

// ============ K3b: reduce partials + faithful scatter ============
__global__ void reduce_kernel(float* __restrict__ out) {
    int idx = blockIdx.x * blockDim.x + threadIdx.x;
    if (idx >= BH * D_ * L_) return;
    int l  = idx & (L_ - 1);
    int dd = (idx >> 11) & (D_ - 1);
    int bh = idx >> 17;
    int b  = bh >> 3, h = bh & 7;
    float v = g_Opart[idx] + g_Opart[BH * D_ * L_ + idx];
    int row = dd * 32 + h * 4 + (l >> 9);
    out[((size_t)b * 2048 + row) * 512 + (l & 511)] = v;
}

// ============ launch ============
extern "C" void kernel_launch(void* const* d_in, const int* in_sizes, int n_in,
                              void* d_out, int out_size) {
    (void)in_sizes; (void)n_in; (void)out_size;
    const float* q = (const float*)d_in[0];
    const float* k = (const float*)d_in[1];
    const float* v = (const float*)d_in[2];
    float* out = (float*)d_out;

    bsplit_kernel<<<(KP * L_ + 255) / 256, 256>>>();
    coeff_kernel<<<B_ * L_, 288>>>(q, k);
    csplit_kernel<<<(int)(((size_t)BH * L_ * KP + 255) / 256), 256>>>();
    z_mma_kernel<<<dim3(16, 16, BH), 256>>>();
    zcombine_kernel<<<(BH * L_ + 255) / 256, 256>>>();
    out_mma_kernel<<<dim3(16, BH, 2), 256>>>(v);
    reduce_kernel<<<(BH * D_ * L_ + 255) / 256, 256>>>(out);
}

// round 7
// speedup vs baseline: 1.3384x; 1.3384x over previous
#include <cuda_runtime.h>
#include <cuda_bf16.h>

#define B_  2
#define L_  2048
#define E_  512
#define H_  8
#define D_  64
#define NC  65
#define KP  240        // [Chi 80][Clo 80][Chi 80] x [Bhi;Bhi;Blo]
#define BH  (B_*H_)

typedef unsigned int uint;

// -------- scratch --------
__device__ float g_C[(size_t)BH * L_ * NC];
__device__ __nv_bfloat16 gCs[(size_t)BH * L_ * KP];     // 15.7 MB  [bh*L+s][240]
__device__ __nv_bfloat16 gBt[L_ * KP];                  // 0.98 MB  [t][240]
__device__ float g_Zp[16 * BH * L_];
__device__ float g_invZ[BH * L_];
__device__ __nv_bfloat16 g_Phi[(size_t)BH * L_ * L_];   // 134 MB [bh][s][t]
__device__ __nv_bfloat16 g_Plo[(size_t)BH * L_ * L_];   // 134 MB
__device__ float g_Opart[2 * BH * D_ * L_];             // 16 MB  [z][bh][d][l]

__device__ __forceinline__ void mma_bf16(float4& c,
                                         uint a0, uint a1, uint a2, uint a3,
                                         uint b0, uint b1) {
    asm volatile(
        "mma.sync.aligned.m16n8k16.row.col.f32.bf16.bf16.f32 "
        "{%0,%1,%2,%3}, {%4,%5,%6,%7}, {%8,%9}, {%0,%1,%2,%3};"
        : "+f"(c.x), "+f"(c.y), "+f"(c.z), "+f"(c.w)
        : "r"(a0), "r"(a1), "r"(a2), "r"(a3), "r"(b0), "r"(b1));
}
__device__ __forceinline__ void ldsm_x4(uint& r0, uint& r1, uint& r2, uint& r3,
                                        const void* p) {
    uint a = (uint)__cvta_generic_to_shared(p);
    asm volatile("ldmatrix.sync.aligned.m8n8.x4.shared.b16 {%0,%1,%2,%3}, [%4];"
                 : "=r"(r0), "=r"(r1), "=r"(r2), "=r"(r3) : "r"(a));
}
__device__ __forceinline__ void ldsm_x4_t(uint& r0, uint& r1, uint& r2, uint& r3,
                                          const void* p) {
    uint a = (uint)__cvta_generic_to_shared(p);
    asm volatile("ldmatrix.sync.aligned.m8n8.x4.trans.shared.b16 {%0,%1,%2,%3}, [%4];"
                 : "=r"(r0), "=r"(r1), "=r"(r2), "=r"(r3) : "r"(a));
}
__device__ __forceinline__ uint pack_hi(float x, float y) {
    __nv_bfloat162 h = __floats2bfloat162_rn(x, y);
    return *(uint*)&h;
}

// ============ K0: transposed split basis gBt[t][240] ============
__global__ void btsplit_kernel() {
    int idx = blockIdx.x * blockDim.x + threadIdx.x;
    if (idx >= L_ * KP) return;
    int r = idx % KP, t = idx / KP;
    int k = r % 80, part = r / 80;          // part 0,1 -> hi ; 2 -> lo
    float v = 0.f;
    if (k == 0) v = 1.0f;
    else if (k < NC) {
        int f = (k + 1) >> 1;
        int ph = (f * t) & (L_ - 1);
        float s, c;
        sincospif((float)ph * (1.0f / 1024.0f), &s, &c);
        v = (k & 1) ? c : s;
    }
    __nv_bfloat16 hv = __float2bfloat16(v);
    if (part == 2) hv = __float2bfloat16(v - __bfloat162float(hv));
    gBt[idx] = hv;
}

// ============ K1: 64-pt DFTs -> coeffs (fp32), head-mean subtracted ============
__global__ __launch_bounds__(288) void coeff_kernel(const float* __restrict__ q,
                                                    const float* __restrict__ kin) {
    int bs = blockIdx.x;
    int b  = bs >> 11;
    int s  = bs & (L_ - 1);

    __shared__ float sq[E_], sk[E_];
    __shared__ float twc[64], tws[64];
    __shared__ float A[H_][NC];

    int tid = threadIdx.x;
    for (int i = tid; i < E_; i += blockDim.x) {
        sq[i] = q[(size_t)bs * E_ + i];
        sk[i] = kin[(size_t)bs * E_ + i];
    }
    if (tid < 64) {
        float ss, cc;
        sincospif((float)tid * (1.0f / 32.0f), &ss, &cc);
        twc[tid] = cc; tws[tid] = ss;
    }
    __syncthreads();

    if (tid < H_ * 33) {
        int h = tid / 33, f = tid % 33;
        const float* qh = sq + h * D_;
        const float* kh = sk + h * D_;
        float Qr = 0.f, Qi = 0.f, Kr = 0.f, Ki = 0.f;
#pragma unroll 8
        for (int j = 0; j < 64; j++) {
            int m = (f * j) & 63;
            float c = twc[m], sn = tws[m];
            float qq = qh[j], kk2 = kh[j];
            Qr = fmaf(qq, c, Qr);  Qi = fmaf(-qq, sn, Qi);
            Kr = fmaf(kk2, c, Kr); Ki = fmaf(-kk2, sn, Ki);
        }
        float Xr = Qr * Kr + Qi * Ki;
        float Xi = Qi * Kr - Qr * Ki;
        if (f == 0) {
            A[h][0] = Xr * (1.0f / 2048.0f);
        } else {
            A[h][2 * f - 1] =  Xr * (1.0f / 1024.0f);
            A[h][2 * f]     = -Xi * (1.0f / 1024.0f);
        }
    }
    __syncthreads();

    for (int idx = tid; idx < H_ * NC; idx += blockDim.x) {
        int h = idx / NC, kk = idx % NC;
        float m = 0.f;
#pragma unroll
        for (int hh = 0; hh < H_; hh++) m += A[hh][kk];
        m *= (1.0f / H_);
        g_C[((size_t)(b * H_ + h) * L_ + s) * NC + kk] = A[h][kk] - m;
    }
}

// ============ K1b: split coeffs gCs[bh*L+s][240] ============
__global__ void csplit_kernel() {
    size_t idx = (size_t)blockIdx.x * blockDim.x + threadIdx.x;
    if (idx >= (size_t)BH * L_ * KP) return;
    int c = (int)(idx % KP);
    size_t bs = idx / KP;
    int k = c % 80, part = c / 80;          // part 0,2 -> hi ; 1 -> lo
    float x = (k < NC) ? g_C[bs * NC + k] : 0.f;
    __nv_bfloat16 hv = __float2bfloat16(x);
    if (part == 1) hv = __float2bfloat16(x - __bfloat162float(hv));
    gCs[idx] = hv;
}

// ============ K2: tensor corr GEMM + exp -> split-bf16 P, partial rowsum ====
// grid (16 t, 16 s, 16 bh), 256 thr, CTA tile 128x128, K=240 (5 chunks of 48)
#define PCH 56
__global__ __launch_bounds__(256) void z_mma_kernel() {
    int bh    = blockIdx.z;
    int sbase = blockIdx.y * 128;
    int tbase = blockIdx.x * 128;

    __shared__ __align__(16) __nv_bfloat16 As[128 * PCH];    // [s][k]  14 KB
    __shared__ __align__(16) __nv_bfloat16 Bts[128 * PCH];   // [t][k]  14 KB
    __shared__ float zsh[128];

    int tid = threadIdx.x;
    int lane = tid & 31, wid = tid >> 5;
    int g = lane >> 2, tg = lane & 3;
    int mat = lane >> 3, mr = lane & 7;
    int wm = wid >> 2, wn = wid & 3;        // warp tile m64 n32

    if (tid < 128) zsh[tid] = 0.f;

    float4 acc[4][4];
#pragma unroll
    for (int i = 0; i < 4; i++)
#pragma unroll
        for (int j = 0; j < 4; j++) acc[i][j] = make_float4(0.f, 0.f, 0.f, 0.f);

    const size_t abase = ((size_t)bh * L_ + sbase) * KP;

    for (int ch = 0; ch < 5; ch++) {
        __syncthreads();
        {   // stage A [128 s][48 k] + B [128 t][48 k] — pure uint4 copies
            int row = tid >> 1, part = tid & 1;
#pragma unroll
            for (int j = 0; j < 3; j++) {
                int c8 = (part * 3 + j) * 8;
                *(uint4*)(As + row * PCH + c8) =
                    *(const uint4*)(gCs + abase + (size_t)row * KP + ch * 48 + c8);
                *(uint4*)(Bts + row * PCH + c8) =
                    *(const uint4*)(gBt + (size_t)(tbase + row) * KP + ch * 48 + c8);
            }
        }
        __syncthreads();

#pragma unroll
        for (int ks = 0; ks < 3; ks++) {
            int kofs = ks * 16;
            uint a[4][4], bb[4][2];
#pragma unroll
            for (int mi = 0; mi < 4; mi++) {
                int row = wm * 64 + mi * 16 + (mat & 1) * 8 + mr;
                int col = kofs + (mat >> 1) * 8;
                ldsm_x4(a[mi][0], a[mi][1], a[mi][2], a[mi][3], &As[row * PCH + col]);
            }
#pragma unroll
            for (int nj = 0; nj < 2; nj++) {
                int row = wn * 32 + nj * 16 + (mat >> 1) * 8 + mr;
                int col = kofs + (mat & 1) * 8;
                ldsm_x4(bb[2 * nj][0], bb[2 * nj][1], bb[2 * nj + 1][0], bb[2 * nj + 1][1],
                        &Bts[row * PCH + col]);
            }
#pragma unroll
            for (int mi = 0; mi < 4; mi++)
#pragma unroll
                for (int ni = 0; ni < 4; ni++)
                    mma_bf16(acc[mi][ni], a[mi][0], a[mi][1], a[mi][2], a[mi][3],
                             bb[ni][0], bb[ni][1]);
        }
    }

    // epilogue: exp, split-bf16 store, rowsum partials
    const size_t Pb = (size_t)bh * L_ * L_;
    float zl[4][2];
#pragma unroll
    for (int mi = 0; mi < 4; mi++) { zl[mi][0] = 0.f; zl[mi][1] = 0.f; }
#pragma unroll
    for (int mi = 0; mi < 4; mi++) {
        int r0 = sbase + wm * 64 + mi * 16 + g;
#pragma unroll
        for (int ni = 0; ni < 4; ni++) {
            int tc = tbase + wn * 32 + ni * 8 + 2 * tg;
            float4 c = acc[mi][ni];
            float e0 = __expf(c.x), e1 = __expf(c.y);
            float e2 = __expf(c.z), e3 = __expf(c.w);
            zl[mi][0] += e0 + e1;
            zl[mi][1] += e2 + e3;
            __nv_bfloat162 h01 = __floats2bfloat162_rn(e0, e1);
            __nv_bfloat162 h23 = __floats2bfloat162_rn(e2, e3);
            float2 hf01 = __bfloat1622float2(h01);
            float2 hf23 = __bfloat1622float2(h23);
            *(uint*)&g_Phi[Pb + (size_t)r0 * L_ + tc]       = *(uint*)&h01;
            *(uint*)&g_Phi[Pb + (size_t)(r0 + 8) * L_ + tc] = *(uint*)&h23;
            *(uint*)&g_Plo[Pb + (size_t)r0 * L_ + tc]       = pack_hi(e0 - hf01.x, e1 - hf01.y);
            *(uint*)&g_Plo[Pb + (size_t)(r0 + 8) * L_ + tc] = pack_hi(e2 - hf23.x, e3 - hf23.y);
        }
    }
#pragma unroll
    for (int mi = 0; mi < 4; mi++)
#pragma unroll
        for (int hh = 0; hh < 2; hh++) {
            float v = zl[mi][hh];
            v += __shfl_xor_sync(0xffffffffu, v, 1);
            v += __shfl_xor_sync(0xffffffffu, v, 2);
            if (tg == 0) atomicAdd(&zsh[wm * 64 + mi * 16 + g + hh * 8], v);
        }
    __syncthreads();
    if (tid < 128)
        g_Zp[((size_t)blockIdx.x * BH + bh) * L_ + sbase + tid] = zsh[tid];
}

// ============ K2b: combine 16 t-tile partials -> invZ ============
__global__ void zcombine_kernel() {
    int i = blockIdx.x * blockDim.x + threadIdx.x;
    if (i >= BH * L_) return;
    float z = 0.f;
#pragma unroll
    for (int tt = 0; tt < 16; tt++) z += g_Zp[(size_t)tt * (BH * L_) + i];
    g_invZ[i] = 1.0f / z;
}

// ============ K3: tensor out GEMM (split-bf16 P staged raw, invZ folded in V) =
// grid (16 l, 16 bh, 2 s-halves), 256 thr, CTA tile 128(l) x 64(d), chunk 32 s.
#define LDA3 136
#define LDV3 72
__global__ __launch_bounds__(256) void out_mma_kernel(const float* __restrict__ values) {
    int bh = blockIdx.y;
    int b  = bh >> 3, h = bh & 7;
    int lbase = blockIdx.x * 128;
    int zhalf = blockIdx.z;

    __shared__ __align__(16) char smemraw[33280];
    __nv_bfloat16* Ahi = (__nv_bfloat16*)smemraw;          // [32 s][LDA3]
    __nv_bfloat16* Alo = Ahi + 32 * LDA3;
    __nv_bfloat16* Vhi = Alo + 32 * LDA3;                  // [32 s][LDV3]
    __nv_bfloat16* Vlo = Vhi + 32 * LDV3;
    float* osb = (float*)smemraw;                          // [128 l][65] after loop

    int tid = threadIdx.x;
    int lane = tid & 31, wid = tid >> 5;
    int g = lane >> 2, tg = lane & 3;
    int mat = lane >> 3, mr = lane & 7;
    int wm = wid >> 1, wn = wid & 1;        // warp tile m32(l) n32(d)

    float4 acc[2][4];
#pragma unroll
    for (int i = 0; i < 2; i++)
#pragma unroll
        for (int j = 0; j < 4; j++) acc[i][j] = make_float4(0.f, 0.f, 0.f, 0.f);

    const size_t Pb = (size_t)bh * L_ * L_;
    const float* vptr = values + (size_t)b * L_ * E_ + h * D_;

    for (int sch = 0; sch < 32; sch++) {
        int sbase = zhalf * 1024 + sch * 32;
        __syncthreads();
        {   // stage P tiles raw (no conversion): [32 s][128 l] hi + lo
#pragma unroll
            for (int it = 0; it < 2; it++) {
                int idx = tid + it * 256;
                int sc = idx >> 4, c8 = (idx & 15) * 8;
                *(uint4*)&Ahi[sc * LDA3 + c8] =
                    *(const uint4*)&g_Phi[Pb + (size_t)(sbase + sc) * L_ + lbase + c8];
                *(uint4*)&Alo[sc * LDA3 + c8] =
                    *(const uint4*)&g_Plo[Pb + (size_t)(sbase + sc) * L_ + lbase + c8];
            }
        }
        {   // stage V scaled by invZ, split hi/lo: [32 s][64 d]
            int sc = tid >> 3, dq = tid & 7;
            float iz = g_invZ[bh * L_ + sbase + sc];
#pragma unroll
            for (int j = 0; j < 2; j++) {
                int d4 = dq + 8 * j;
                float4 v4 = *(const float4*)&vptr[(size_t)(sbase + sc) * E_ + d4 * 4];
                v4.x *= iz; v4.y *= iz; v4.z *= iz; v4.w *= iz;
                uint h0 = pack_hi(v4.x, v4.y), h1 = pack_hi(v4.z, v4.w);
                __nv_bfloat162 b0 = *(__nv_bfloat162*)&h0;
                __nv_bfloat162 b1 = *(__nv_bfloat162*)&h1;
                float2 f0 = __bfloat1622float2(b0);
                float2 f1 = __bfloat1622float2(b1);
                uint l0 = pack_hi(v4.x - f0.x, v4.y - f0.y);
                uint l1 = pack_hi(v4.z - f1.x, v4.w - f1.y);
                *(uint2*)&Vhi[sc * LDV3 + d4 * 4] = make_uint2(h0, h1);
                *(uint2*)&Vlo[sc * LDV3 + d4 * 4] = make_uint2(l0, l1);
            }
        }
        __syncthreads();

#pragma unroll
        for (int ks = 0; ks < 2; ks++) {
            int kofs = ks * 16;
            uint ah[2][4], al[2][4], vh[4][2], vl[4][2];
            {   // A via ldmatrix.trans from [s][l]
                int row = kofs + (mat >> 1) * 8 + mr;
#pragma unroll
                for (int mi = 0; mi < 2; mi++) {
                    int col = wm * 32 + mi * 16 + (mat & 1) * 8;
                    ldsm_x4_t(ah[mi][0], ah[mi][1], ah[mi][2], ah[mi][3],
                              &Ahi[row * LDA3 + col]);
                    ldsm_x4_t(al[mi][0], al[mi][1], al[mi][2], al[mi][3],
                              &Alo[row * LDA3 + col]);
                }
            }
            {   // B via ldmatrix.trans from [s][d]
                int row = kofs + (mat & 1) * 8 + mr;
#pragma unroll
                for (int nj = 0; nj < 2; nj++) {
                    int col = wn * 32 + nj * 16 + (mat >> 1) * 8;
                    ldsm_x4_t(vh[2 * nj][0], vh[2 * nj][1], vh[2 * nj + 1][0], vh[2 * nj + 1][1],
                              &Vhi[row * LDV3 + col]);
                    ldsm_x4_t(vl[2 * nj][0], vl[2 * nj][1], vl[2 * nj + 1][0], vl[2 * nj + 1][1],
                              &Vlo[row * LDV3 + col]);
                }
            }
#pragma unroll
            for (int mi = 0; mi < 2; mi++)
#pragma unroll
                for (int ni = 0; ni < 4; ni++) {
                    mma_bf16(acc[mi][ni], ah[mi][0], ah[mi][1], ah[mi][2], ah[mi][3],
                             vh[ni][0], vh[ni][1]);
                    mma_bf16(acc[mi][ni], al[mi][0], al[mi][1], al[mi][2], al[mi][3],
                             vh[ni][0], vh[ni][1]);
                    mma_bf16(acc[mi][ni], ah[mi][0], ah[mi][1], ah[mi][2], ah[mi][3],
                             vl[ni][0], vl[ni][1]);
                }
        }
    }

    __syncthreads();
#pragma unroll
    for (int mi = 0; mi < 2; mi++) {
        int l0 = wm * 32 + mi * 16 + g;
#pragma unroll
        for (int ni = 0; ni < 4; ni++) {
            int d0 = wn * 32 + ni * 8 + 2 * tg;
            float4 c = acc[mi][ni];
            osb[l0 * 65 + d0]           = c.x;
            osb[l0 * 65 + d0 + 1]       = c.y;
            osb[(l0 + 8) * 65 + d0]     = c.z;
            osb[(l0 + 8) * 65 + d0 + 1] = c.w;
        }
    }
    __syncthreads();
    {   // coalesced partial store [d][l]
        int dq = tid >> 2, lq = tid & 3;
        float* op = &g_Opart[(((size_t)zhalf * BH + bh) * D_ + dq) * L_ + lbase];
#pragma unroll
        for (int j = 0; j < 8; j++) {
            int l4 = lq + 4 * j;
            float4 w;
            w.x = osb[(l4 * 4 + 0) * 65 + dq];
            w.y = osb[(l4 * 4 + 1) * 65 + dq];
            w.z = osb[(l4 * 4 + 2) * 65 + dq];
            w.w = osb[(l4 * 4 + 3) * 65 + dq];
            *(float4*)&op[l4 * 4] = w;
        }
    }
}

// ============ K3b: reduce partials + faithful scatter ============
__global__ void reduce_kernel(float* __restrict__ out) {
    int idx = blockIdx.x * blockDim.x + threadIdx.x;
    if (idx >= BH * D_ * L_) return;
    int l  = idx & (L_ - 1);
    int dd = (idx >> 11) & (D_ - 1);
    int bh = idx >> 17;
    int b  = bh >> 3, h = bh & 7;
    float v = g_Opart[idx] + g_Opart[BH * D_ * L_ + idx];
    int row = dd * 32 + h * 4 + (l >> 9);
    out[((size_t)b * 2048 + row) * 512 + (l & 511)] = v;
}

// ============ launch ============
extern "C" void kernel_launch(void* const* d_in, const int* in_sizes, int n_in,
                              void* d_out, int out_size) {
    (void)in_sizes; (void)n_in; (void)out_size;
    const float* q = (const float*)d_in[0];
    const float* k = (const float*)d_in[1];
    const float* v = (const float*)d_in[2];
    float* out = (float*)d_out;

    btsplit_kernel<<<(L_ * KP + 255) / 256, 256>>>();
    coeff_kernel<<<B_ * L_, 288>>>(q, k);
    csplit_kernel<<<(int)(((size_t)BH * L_ * KP + 255) / 256), 256>>>();
    z_mma_kernel<<<dim3(16, 16, BH), 256>>>();
    zcombine_kernel<<<(BH * L_ + 255) / 256, 256>>>();
    out_mma_kernel<<<dim3(16, BH, 2), 256>>>(v);
    reduce_kernel<<<(BH * D_ * L_ + 255) / 256, 256>>>(out);
}

// round 9
// speedup vs baseline: 1.3513x; 1.0097x over previous
#include <cuda_runtime.h>
#include <cuda_bf16.h>

#define B_  2
#define L_  2048
#define E_  512
#define H_  8
#define D_  64
#define NC  65
#define KP  240        // [Chi 80][Clo 80][Chi 80] x [Bhi;Bhi;Blo]
#define BH  (B_*H_)

typedef unsigned int uint;

// -------- scratch --------
__device__ float g_C[(size_t)BH * L_ * NC];
__device__ __nv_bfloat16 gCs[(size_t)BH * L_ * KP];     // 15.7 MB  [bh*L+s][240]
__device__ __nv_bfloat16 gBt[L_ * KP];                  // 0.98 MB  [t][240]
__device__ float g_Zp[16 * BH * L_];
__device__ float g_invZ[BH * L_];
__device__ __nv_bfloat16 g_Phi[(size_t)BH * L_ * L_];   // 134 MB [bh][s][t]
__device__ __nv_bfloat16 g_Plo[(size_t)BH * L_ * L_];   // 134 MB
__device__ float g_Opart[2 * BH * D_ * L_];             // 16 MB  [z][bh][d][l]

__device__ __forceinline__ void mma_bf16(float4& c,
                                         uint a0, uint a1, uint a2, uint a3,
                                         uint b0, uint b1) {
    asm volatile(
        "mma.sync.aligned.m16n8k16.row.col.f32.bf16.bf16.f32 "
        "{%0,%1,%2,%3}, {%4,%5,%6,%7}, {%8,%9}, {%0,%1,%2,%3};"
        : "+f"(c.x), "+f"(c.y), "+f"(c.z), "+f"(c.w)
        : "r"(a0), "r"(a1), "r"(a2), "r"(a3), "r"(b0), "r"(b1));
}
__device__ __forceinline__ void ldsm_x4(uint& r0, uint& r1, uint& r2, uint& r3,
                                        const void* p) {
    uint a = (uint)__cvta_generic_to_shared(p);
    asm volatile("ldmatrix.sync.aligned.m8n8.x4.shared.b16 {%0,%1,%2,%3}, [%4];"
                 : "=r"(r0), "=r"(r1), "=r"(r2), "=r"(r3) : "r"(a));
}
__device__ __forceinline__ void ldsm_x4_t(uint& r0, uint& r1, uint& r2, uint& r3,
                                          const void* p) {
    uint a = (uint)__cvta_generic_to_shared(p);
    asm volatile("ldmatrix.sync.aligned.m8n8.x4.trans.shared.b16 {%0,%1,%2,%3}, [%4];"
                 : "=r"(r0), "=r"(r1), "=r"(r2), "=r"(r3) : "r"(a));
}
__device__ __forceinline__ uint pack_hi(float x, float y) {
    __nv_bfloat162 h = __floats2bfloat162_rn(x, y);
    return *(uint*)&h;
}
__device__ __forceinline__ void cp16(void* smem, const void* gmem) {
    uint a = (uint)__cvta_generic_to_shared(smem);
    asm volatile("cp.async.cg.shared.global [%0], [%1], 16;" :: "r"(a), "l"(gmem));
}
__device__ __forceinline__ void cp_commit() {
    asm volatile("cp.async.commit_group;");
}
template <int N>
__device__ __forceinline__ void cp_wait() {
    asm volatile("cp.async.wait_group %0;" :: "n"(N));
}

// ============ K0: transposed split basis gBt[t][240] ============
__global__ void btsplit_kernel() {
    int idx = blockIdx.x * blockDim.x + threadIdx.x;
    if (idx >= L_ * KP) return;
    int r = idx % KP, t = idx / KP;
    int k = r % 80, part = r / 80;
    float v = 0.f;
    if (k == 0) v = 1.0f;
    else if (k < NC) {
        int f = (k + 1) >> 1;
        int ph = (f * t) & (L_ - 1);
        float s, c;
        sincospif((float)ph * (1.0f / 1024.0f), &s, &c);
        v = (k & 1) ? c : s;
    }
    __nv_bfloat16 hv = __float2bfloat16(v);
    if (part == 2) hv = __float2bfloat16(v - __bfloat162float(hv));
    gBt[idx] = hv;
}

// ============ K1: 64-pt DFTs -> coeffs, head-mean subtracted ============
__global__ __launch_bounds__(288) void coeff_kernel(const float* __restrict__ q,
                                                    const float* __restrict__ kin) {
    int bs = blockIdx.x;
    int b  = bs >> 11;
    int s  = bs & (L_ - 1);

    __shared__ float sq[E_], sk[E_];
    __shared__ float twc[64], tws[64];
    __shared__ float A[H_][NC];

    int tid = threadIdx.x;
    for (int i = tid; i < E_; i += blockDim.x) {
        sq[i] = q[(size_t)bs * E_ + i];
        sk[i] = kin[(size_t)bs * E_ + i];
    }
    if (tid < 64) {
        float ss, cc;
        sincospif((float)tid * (1.0f / 32.0f), &ss, &cc);
        twc[tid] = cc; tws[tid] = ss;
    }
    __syncthreads();

    if (tid < H_ * 33) {
        int h = tid / 33, f = tid % 33;
        const float* qh = sq + h * D_;
        const float* kh = sk + h * D_;
        float Qr = 0.f, Qi = 0.f, Kr = 0.f, Ki = 0.f;
#pragma unroll 8
        for (int j = 0; j < 64; j++) {
            int m = (f * j) & 63;
            float c = twc[m], sn = tws[m];
            float qq = qh[j], kk2 = kh[j];
            Qr = fmaf(qq, c, Qr);  Qi = fmaf(-qq, sn, Qi);
            Kr = fmaf(kk2, c, Kr); Ki = fmaf(-kk2, sn, Ki);
        }
        float Xr = Qr * Kr + Qi * Ki;
        float Xi = Qi * Kr - Qr * Ki;
        if (f == 0) {
            A[h][0] = Xr * (1.0f / 2048.0f);
        } else {
            A[h][2 * f - 1] =  Xr * (1.0f / 1024.0f);
            A[h][2 * f]     = -Xi * (1.0f / 1024.0f);
        }
    }
    __syncthreads();

    for (int idx = tid; idx < H_ * NC; idx += blockDim.x) {
        int h = idx / NC, kk = idx % NC;
        float m = 0.f;
#pragma unroll
        for (int hh = 0; hh < H_; hh++) m += A[hh][kk];
        m *= (1.0f / H_);
        g_C[((size_t)(b * H_ + h) * L_ + s) * NC + kk] = A[h][kk] - m;
    }
}

// ============ K1b: split coeffs gCs[bh*L+s][240] ============
__global__ void csplit_kernel() {
    size_t idx = (size_t)blockIdx.x * blockDim.x + threadIdx.x;
    if (idx >= (size_t)BH * L_ * KP) return;
    int c = (int)(idx % KP);
    size_t bs = idx / KP;
    int k = c % 80, part = c / 80;
    float x = (k < NC) ? g_C[bs * NC + k] : 0.f;
    __nv_bfloat16 hv = __float2bfloat16(x);
    if (part == 1) hv = __float2bfloat16(x - __bfloat162float(hv));
    gCs[idx] = hv;
}

// ============ K2: pipelined tensor corr GEMM + exp -> split P ============
// grid (16 t, 16 s, 16 bh), 256 thr, CTA 128x128, K=240, 5 chunks of 48, 2-deep
#define PCH 56
#define ABUF (128 * PCH)
__global__ __launch_bounds__(256) void z_mma_kernel() {
    int bh    = blockIdx.z;
    int sbase = blockIdx.y * 128;
    int tbase = blockIdx.x * 128;

    __shared__ __align__(16) __nv_bfloat16 As[2 * ABUF];    // 28 KB
    __shared__ __align__(16) __nv_bfloat16 Bts[2 * ABUF];   // 28 KB
    __shared__ float zsh[128];

    int tid = threadIdx.x;
    int lane = tid & 31, wid = tid >> 5;
    int g = lane >> 2, tg = lane & 3;
    int mat = lane >> 3, mr = lane & 7;
    int wm = wid >> 2, wn = wid & 3;

    if (tid < 128) zsh[tid] = 0.f;

    float4 acc[4][4];
#pragma unroll
    for (int i = 0; i < 4; i++)
#pragma unroll
        for (int j = 0; j < 4; j++) acc[i][j] = make_float4(0.f, 0.f, 0.f, 0.f);

    const size_t abase = ((size_t)bh * L_ + sbase) * KP;
    int srow = tid >> 1, spart = tid & 1;

    // prologue: stage chunk 0 into buf 0
#pragma unroll
    for (int j = 0; j < 3; j++) {
        int c8 = (spart * 3 + j) * 8;
        cp16(As + srow * PCH + c8, gCs + abase + (size_t)srow * KP + c8);
        cp16(Bts + srow * PCH + c8, gBt + (size_t)(tbase + srow) * KP + c8);
    }
    cp_commit();

    for (int ch = 0; ch < 5; ch++) {
        int buf = ch & 1;
        if (ch < 4) {
            int nb = (ch + 1) & 1;
#pragma unroll
            for (int j = 0; j < 3; j++) {
                int c8 = (spart * 3 + j) * 8;
                cp16(As + nb * ABUF + srow * PCH + c8,
                     gCs + abase + (size_t)srow * KP + (ch + 1) * 48 + c8);
                cp16(Bts + nb * ABUF + srow * PCH + c8,
                     gBt + (size_t)(tbase + srow) * KP + (ch + 1) * 48 + c8);
            }
            cp_commit();
            cp_wait<1>();
        } else {
            cp_wait<0>();
        }
        __syncthreads();

        const __nv_bfloat16* Ab = As + buf * ABUF;
        const __nv_bfloat16* Bb = Bts + buf * ABUF;
#pragma unroll
        for (int ks = 0; ks < 3; ks++) {
            int kofs = ks * 16;
            uint a[4][4], bb[4][2];
#pragma unroll
            for (int mi = 0; mi < 4; mi++) {
                int row = wm * 64 + mi * 16 + (mat & 1) * 8 + mr;
                int col = kofs + (mat >> 1) * 8;
                ldsm_x4(a[mi][0], a[mi][1], a[mi][2], a[mi][3], &Ab[row * PCH + col]);
            }
#pragma unroll
            for (int nj = 0; nj < 2; nj++) {
                int row = wn * 32 + nj * 16 + (mat >> 1) * 8 + mr;
                int col = kofs + (mat & 1) * 8;
                ldsm_x4(bb[2 * nj][0], bb[2 * nj][1], bb[2 * nj + 1][0], bb[2 * nj + 1][1],
                        &Bb[row * PCH + col]);
            }
#pragma unroll
            for (int mi = 0; mi < 4; mi++)
#pragma unroll
                for (int ni = 0; ni < 4; ni++)
                    mma_bf16(acc[mi][ni], a[mi][0], a[mi][1], a[mi][2], a[mi][3],
                             bb[ni][0], bb[ni][1]);
        }
        __syncthreads();
    }

    // epilogue: exp, split-bf16 store, rowsum partials
    const size_t Pb = (size_t)bh * L_ * L_;
    float zl[4][2];
#pragma unroll
    for (int mi = 0; mi < 4; mi++) { zl[mi][0] = 0.f; zl[mi][1] = 0.f; }
#pragma unroll
    for (int mi = 0; mi < 4; mi++) {
        int r0 = sbase + wm * 64 + mi * 16 + g;
#pragma unroll
        for (int ni = 0; ni < 4; ni++) {
            int tc = tbase + wn * 32 + ni * 8 + 2 * tg;
            float4 c = acc[mi][ni];
            float e0 = __expf(c.x), e1 = __expf(c.y);
            float e2 = __expf(c.z), e3 = __expf(c.w);
            zl[mi][0] += e0 + e1;
            zl[mi][1] += e2 + e3;
            __nv_bfloat162 h01 = __floats2bfloat162_rn(e0, e1);
            __nv_bfloat162 h23 = __floats2bfloat162_rn(e2, e3);
            float2 hf01 = __bfloat1622float2(h01);
            float2 hf23 = __bfloat1622float2(h23);
            *(uint*)&g_Phi[Pb + (size_t)r0 * L_ + tc]       = *(uint*)&h01;
            *(uint*)&g_Phi[Pb + (size_t)(r0 + 8) * L_ + tc] = *(uint*)&h23;
            *(uint*)&g_Plo[Pb + (size_t)r0 * L_ + tc]       = pack_hi(e0 - hf01.x, e1 - hf01.y);
            *(uint*)&g_Plo[Pb + (size_t)(r0 + 8) * L_ + tc] = pack_hi(e2 - hf23.x, e3 - hf23.y);
        }
    }
#pragma unroll
    for (int mi = 0; mi < 4; mi++)
#pragma unroll
        for (int hh = 0; hh < 2; hh++) {
            float v = zl[mi][hh];
            v += __shfl_xor_sync(0xffffffffu, v, 1);
            v += __shfl_xor_sync(0xffffffffu, v, 2);
            if (tg == 0) atomicAdd(&zsh[wm * 64 + mi * 16 + g + hh * 8], v);
        }
    __syncthreads();
    if (tid < 128)
        g_Zp[((size_t)blockIdx.x * BH + bh) * L_ + sbase + tid] = zsh[tid];
}

// ============ K2b: combine partials -> invZ ============
__global__ void zcombine_kernel() {
    int i = blockIdx.x * blockDim.x + threadIdx.x;
    if (i >= BH * L_) return;
    float z = 0.f;
#pragma unroll
    for (int tt = 0; tt < 16; tt++) z += g_Zp[(size_t)tt * (BH * L_) + i];
    g_invZ[i] = 1.0f / z;
}

// ============ K3: pipelined tensor out GEMM ============
// grid (16 l, 16 bh, 2 s-halves), 256 thr, CTA 128(l) x 64(d), 32 chunks of 32 s
#define LDA3 136
#define LDV3 72
#define PBUF (32 * LDA3)
#define VBUF (32 * LDV3)
__global__ __launch_bounds__(256) void out_mma_kernel(const float* __restrict__ values) {
    int bh = blockIdx.y;
    int b  = bh >> 3, h = bh & 7;
    int lbase = blockIdx.x * 128;
    int zhalf = blockIdx.z;

    __shared__ __align__(16) char smemraw[53248];
    __nv_bfloat16* Ahi0 = (__nv_bfloat16*)smemraw;   // [2][PBUF]
    __nv_bfloat16* Alo0 = Ahi0 + 2 * PBUF;
    __nv_bfloat16* Vhi0 = Alo0 + 2 * PBUF;           // [2][VBUF]
    __nv_bfloat16* Vlo0 = Vhi0 + 2 * VBUF;
    float* osb = (float*)smemraw;                    // [128][65] after loop

    int tid = threadIdx.x;
    int lane = tid & 31, wid = tid >> 5;
    int g = lane >> 2, tg = lane & 3;
    int mat = lane >> 3, mr = lane & 7;
    int wm = wid >> 1, wn = wid & 1;

    float4 acc[2][4];
#pragma unroll
    for (int i = 0; i < 2; i++)
#pragma unroll
        for (int j = 0; j < 4; j++) acc[i][j] = make_float4(0.f, 0.f, 0.f, 0.f);

    const size_t Pb = (size_t)bh * L_ * L_;
    const float* vptr = values + (size_t)b * L_ * E_ + h * D_;

    int psc0 = tid >> 4, pc8_0 = (tid & 15) * 8;     // P staging coords (2 iters)
    int vsc = tid >> 3, vdq = tid & 7;               // V staging coords

    // ---- prologue: chunk 0 ----
    {
        int sbase = zhalf * 1024;
#pragma unroll
        for (int it = 0; it < 2; it++) {
            int sc = psc0 + it * 16;
            cp16(&Ahi0[sc * LDA3 + pc8_0], &g_Phi[Pb + (size_t)(sbase + sc) * L_ + lbase + pc8_0]);
            cp16(&Alo0[sc * LDA3 + pc8_0], &g_Plo[Pb + (size_t)(sbase + sc) * L_ + lbase + pc8_0]);
        }
        cp_commit();
        float iz = g_invZ[bh * L_ + sbase + vsc];
#pragma unroll
        for (int j = 0; j < 2; j++) {
            int d4 = vdq + 8 * j;
            float4 v4 = *(const float4*)&vptr[(size_t)(sbase + vsc) * E_ + d4 * 4];
            v4.x *= iz; v4.y *= iz; v4.z *= iz; v4.w *= iz;
            uint h0 = pack_hi(v4.x, v4.y), h1 = pack_hi(v4.z, v4.w);
            __nv_bfloat162 b0 = *(__nv_bfloat162*)&h0;
            __nv_bfloat162 b1 = *(__nv_bfloat162*)&h1;
            float2 f0 = __bfloat1622float2(b0);
            float2 f1 = __bfloat1622float2(b1);
            *(uint2*)&Vhi0[vsc * LDV3 + d4 * 4] = make_uint2(h0, h1);
            *(uint2*)&Vlo0[vsc * LDV3 + d4 * 4] =
                make_uint2(pack_hi(v4.x - f0.x, v4.y - f0.y), pack_hi(v4.z - f1.x, v4.w - f1.y));
        }
    }

    for (int sch = 0; sch < 32; sch++) {
        int buf = sch & 1;
        float4 vr[2];
        float vizn = 0.f;
        if (sch < 31) {
            int nb = (sch + 1) & 1;
            int nsb = zhalf * 1024 + (sch + 1) * 32;
#pragma unroll
            for (int it = 0; it < 2; it++) {
                int sc = psc0 + it * 16;
                cp16(&Ahi0[nb * PBUF + sc * LDA3 + pc8_0],
                     &g_Phi[Pb + (size_t)(nsb + sc) * L_ + lbase + pc8_0]);
                cp16(&Alo0[nb * PBUF + sc * LDA3 + pc8_0],
                     &g_Plo[Pb + (size_t)(nsb + sc) * L_ + lbase + pc8_0]);
            }
            cp_commit();
            vizn = g_invZ[bh * L_ + nsb + vsc];
            vr[0] = *(const float4*)&vptr[(size_t)(nsb + vsc) * E_ + vdq * 4];
            vr[1] = *(const float4*)&vptr[(size_t)(nsb + vsc) * E_ + vdq * 4 + 32];
            cp_wait<1>();
        } else {
            cp_wait<0>();
        }
        __syncthreads();

        const __nv_bfloat16* Ahi = Ahi0 + buf * PBUF;
        const __nv_bfloat16* Alo = Alo0 + buf * PBUF;
        const __nv_bfloat16* Vhi = Vhi0 + buf * VBUF;
        const __nv_bfloat16* Vlo = Vlo0 + buf * VBUF;

#pragma unroll
        for (int ks = 0; ks < 2; ks++) {
            int kofs = ks * 16;
            uint ah[2][4], al[2][4], vh[4][2], vl[4][2];
            {
                int row = kofs + (mat >> 1) * 8 + mr;
#pragma unroll
                for (int mi = 0; mi < 2; mi++) {
                    int col = wm * 32 + mi * 16 + (mat & 1) * 8;
                    ldsm_x4_t(ah[mi][0], ah[mi][1], ah[mi][2], ah[mi][3],
                              &Ahi[row * LDA3 + col]);
                    ldsm_x4_t(al[mi][0], al[mi][1], al[mi][2], al[mi][3],
                              &Alo[row * LDA3 + col]);
                }
            }
            {
                int row = kofs + (mat & 1) * 8 + mr;
#pragma unroll
                for (int nj = 0; nj < 2; nj++) {
                    int col = wn * 32 + nj * 16 + (mat >> 1) * 8;
                    ldsm_x4_t(vh[2 * nj][0], vh[2 * nj][1], vh[2 * nj + 1][0], vh[2 * nj + 1][1],
                              &Vhi[row * LDV3 + col]);
                    ldsm_x4_t(vl[2 * nj][0], vl[2 * nj][1], vl[2 * nj + 1][0], vl[2 * nj + 1][1],
                              &Vlo[row * LDV3 + col]);
                }
            }
#pragma unroll
            for (int mi = 0; mi < 2; mi++)
#pragma unroll
                for (int ni = 0; ni < 4; ni++) {
                    mma_bf16(acc[mi][ni], ah[mi][0], ah[mi][1], ah[mi][2], ah[mi][3],
                             vh[ni][0], vh[ni][1]);
                    mma_bf16(acc[mi][ni], al[mi][0], al[mi][1], al[mi][2], al[mi][3],
                             vh[ni][0], vh[ni][1]);
                    mma_bf16(acc[mi][ni], ah[mi][0], ah[mi][1], ah[mi][2], ah[mi][3],
                             vl[ni][0], vl[ni][1]);
                }
        }

        if (sch < 31) {   // STS prefetched V into alternate buffer
            int nb = (sch + 1) & 1;
#pragma unroll
            for (int j = 0; j < 2; j++) {
                int d4 = vdq + 8 * j;
                float4 v4 = vr[j];
                v4.x *= vizn; v4.y *= vizn; v4.z *= vizn; v4.w *= vizn;
                uint h0 = pack_hi(v4.x, v4.y), h1 = pack_hi(v4.z, v4.w);
                __nv_bfloat162 b0 = *(__nv_bfloat162*)&h0;
                __nv_bfloat162 b1 = *(__nv_bfloat162*)&h1;
                float2 f0 = __bfloat1622float2(b0);
                float2 f1 = __bfloat1622float2(b1);
                *(uint2*)&Vhi0[nb * VBUF + vsc * LDV3 + d4 * 4] = make_uint2(h0, h1);
                *(uint2*)&Vlo0[nb * VBUF + vsc * LDV3 + d4 * 4] =
                    make_uint2(pack_hi(v4.x - f0.x, v4.y - f0.y),
                               pack_hi(v4.z - f1.x, v4.w - f1.y));
            }
        }
        __syncthreads();
    }

    // accums -> osb[l][65]
#pragma unroll
    for (int mi = 0; mi < 2; mi++) {
        int l0 = wm * 32 + mi * 16 + g;
#pragma unroll
        for (int ni = 0; ni < 4; ni++) {
            int d0 = wn * 32 + ni * 8 + 2 * tg;
            float4 c = acc[mi][ni];
            osb[l0 * 65 + d0]           = c.x;
            osb[l0 * 65 + d0 + 1]       = c.y;
            osb[(l0 + 8) * 65 + d0]     = c.z;
            osb[(l0 + 8) * 65 + d0 + 1] = c.w;
        }
    }
    __syncthreads();
    {
        int dq = tid >> 2, lq = tid & 3;
        float* op = &g_Opart[(((size_t)zhalf * BH + bh) * D_ + dq) * L_ + lbase];
#pragma unroll
        for (int j = 0; j < 8; j++) {
            int l4 = lq + 4 * j;
            float4 w;
            w.x = osb[(l4 * 4 + 0) * 65 + dq];
            w.y = osb[(l4 * 4 + 1) * 65 + dq];
            w.z = osb[(l4 * 4 + 2) * 65 + dq];
            w.w = osb[(l4 * 4 + 3) * 65 + dq];
            *(float4*)&op[l4 * 4] = w;
        }
    }
}

// ============ K3b: reduce partials + faithful scatter ============
__global__ void reduce_kernel(float* __restrict__ out) {
    int idx = blockIdx.x * blockDim.x + threadIdx.x;
    if (idx >= BH * D_ * L_) return;
    int l  = idx & (L_ - 1);
    int dd = (idx >> 11) & (D_ - 1);
    int bh = idx >> 17;
    int b  = bh >> 3, h = bh & 7;
    float v = g_Opart[idx] + g_Opart[BH * D_ * L_ + idx];
    int row = dd * 32 + h * 4 + (l >> 9);
    out[((size_t)b * 2048 + row) * 512 + (l & 511)] = v;
}

// ============ launch ============
extern "C" void kernel_launch(void* const* d_in, const int* in_sizes, int n_in,
                              void* d_out, int out_size) {
    (void)in_sizes; (void)n_in; (void)out_size;
    const float* q = (const float*)d_in[0];
    const float* k = (const float*)d_in[1];
    const float* v = (const float*)d_in[2];
    float* out = (float*)d_out;

    btsplit_kernel<<<(L_ * KP + 255) / 256, 256>>>();
    coeff_kernel<<<B_ * L_, 288>>>(q, k);
    csplit_kernel<<<(int)(((size_t)BH * L_ * KP + 255) / 256), 256>>>();
    z_mma_kernel<<<dim3(16, 16, BH), 256>>>();
    zcombine_kernel<<<(BH * L_ + 255) / 256, 256>>>();
    out_mma_kernel<<<dim3(16, BH, 2), 256>>>(v);
    reduce_kernel<<<(BH * D_ * L_ + 255) / 256, 256>>>(out);
}

// round 11
// speedup vs baseline: 1.5198x; 1.1247x over previous
#include <cuda_runtime.h>
#include <cuda_bf16.h>
#include <cuda_fp16.h>

#define B_  2
#define L_  2048
#define E_  512
#define H_  8
#define D_  64
#define NC  65
#define KPZ 160        // fp16 split-K for K2: [Chi 65 |pad| ][Clo 65 |pad|]
#define BH  (B_*H_)

typedef unsigned int uint;

// -------- scratch --------
__device__ float g_C[(size_t)BH * L_ * NC];
__device__ __half gCz[(size_t)BH * L_ * KPZ];           // 10.5 MB [bh*L+s][160]
__device__ __half gBz[L_ * KPZ];                        // 0.66 MB [t][160]
__device__ float g_Zp[16 * BH * L_];
__device__ float g_invZ[BH * L_];
__device__ __nv_bfloat16 g_Phi[(size_t)BH * L_ * L_];   // 134 MB [bh][s][t]
__device__ __nv_bfloat16 g_Plo[(size_t)BH * L_ * L_];   // 134 MB
__device__ float g_Opart[2 * BH * D_ * L_];             // 16 MB  [z][bh][d][l]

// ---------------- helpers ----------------
__device__ __forceinline__ uint smem_u32(const void* p) {
    uint a;
    asm("{ .reg .u64 t; cvta.to.shared.u64 t, %1; cvt.u32.u64 %0, t; }" : "=r"(a) : "l"(p));
    return a;
}
__device__ __forceinline__ void mma_bf16(float4& c,
                                         uint a0, uint a1, uint a2, uint a3,
                                         uint b0, uint b1) {
    asm volatile(
        "mma.sync.aligned.m16n8k16.row.col.f32.bf16.bf16.f32 "
        "{%0,%1,%2,%3}, {%4,%5,%6,%7}, {%8,%9}, {%0,%1,%2,%3};"
        : "+f"(c.x), "+f"(c.y), "+f"(c.z), "+f"(c.w)
        : "r"(a0), "r"(a1), "r"(a2), "r"(a3), "r"(b0), "r"(b1));
}
__device__ __forceinline__ void mma_fp16(float4& c,
                                         uint a0, uint a1, uint a2, uint a3,
                                         uint b0, uint b1) {
    asm volatile(
        "mma.sync.aligned.m16n8k16.row.col.f32.f16.f16.f32 "
        "{%0,%1,%2,%3}, {%4,%5,%6,%7}, {%8,%9}, {%0,%1,%2,%3};"
        : "+f"(c.x), "+f"(c.y), "+f"(c.z), "+f"(c.w)
        : "r"(a0), "r"(a1), "r"(a2), "r"(a3), "r"(b0), "r"(b1));
}
__device__ __forceinline__ void ldsm_x4(uint& r0, uint& r1, uint& r2, uint& r3,
                                        const void* p) {
    uint a = smem_u32(p);
    asm volatile("ldmatrix.sync.aligned.m8n8.x4.shared.b16 {%0,%1,%2,%3}, [%4];"
                 : "=r"(r0), "=r"(r1), "=r"(r2), "=r"(r3) : "r"(a));
}
__device__ __forceinline__ void ldsm_x4_t(uint& r0, uint& r1, uint& r2, uint& r3,
                                          const void* p) {
    uint a = smem_u32(p);
    asm volatile("ldmatrix.sync.aligned.m8n8.x4.trans.shared.b16 {%0,%1,%2,%3}, [%4];"
                 : "=r"(r0), "=r"(r1), "=r"(r2), "=r"(r3) : "r"(a));
}
__device__ __forceinline__ uint pack_hi(float x, float y) {
    __nv_bfloat162 h = __floats2bfloat162_rn(x, y);
    return *(uint*)&h;
}
__device__ __forceinline__ void cp16g(void* smem, const void* gmem) {
    uint a = smem_u32(smem);
    asm volatile("cp.async.cg.shared.global [%0], [%1], 16;" :: "r"(a), "l"(gmem));
}
__device__ __forceinline__ void cp_commit() { asm volatile("cp.async.commit_group;"); }
template <int N> __device__ __forceinline__ void cp_wait() {
    asm volatile("cp.async.wait_group %0;" :: "n"(N));
}

// ============ K0: fp16 basis gBz[t][160] (same value at k and 80+k) ============
__global__ void btsplit_kernel() {
    int idx = blockIdx.x * blockDim.x + threadIdx.x;
    if (idx >= L_ * KPZ) return;
    int r = idx % KPZ, t = idx / KPZ;
    int k = r % 80;
    float v = 0.f;
    if (k == 0) v = 1.0f;
    else if (k < NC) {
        int f = (k + 1) >> 1;
        int ph = (f * t) & (L_ - 1);
        float s, c;
        sincospif((float)ph * (1.0f / 1024.0f), &s, &c);
        v = (k & 1) ? c : s;
    }
    gBz[idx] = __float2half(v);
}

// ============ K1: 64-pt DFTs -> coeffs, head-mean subtracted ============
__global__ __launch_bounds__(288) void coeff_kernel(const float* __restrict__ q,
                                                    const float* __restrict__ kin) {
    int bs = blockIdx.x;
    int b  = bs >> 11;
    int s  = bs & (L_ - 1);

    __shared__ float sq[E_], sk[E_];
    __shared__ float twc[64], tws[64];
    __shared__ float A[H_][NC];

    int tid = threadIdx.x;
    for (int i = tid; i < E_; i += blockDim.x) {
        sq[i] = q[(size_t)bs * E_ + i];
        sk[i] = kin[(size_t)bs * E_ + i];
    }
    if (tid < 64) {
        float ss, cc;
        sincospif((float)tid * (1.0f / 32.0f), &ss, &cc);
        twc[tid] = cc; tws[tid] = ss;
    }
    __syncthreads();

    if (tid < H_ * 33) {
        int h = tid / 33, f = tid % 33;
        const float* qh = sq + h * D_;
        const float* kh = sk + h * D_;
        float Qr = 0.f, Qi = 0.f, Kr = 0.f, Ki = 0.f;
#pragma unroll 8
        for (int j = 0; j < 64; j++) {
            int m = (f * j) & 63;
            float c = twc[m], sn = tws[m];
            float qq = qh[j], kk2 = kh[j];
            Qr = fmaf(qq, c, Qr);  Qi = fmaf(-qq, sn, Qi);
            Kr = fmaf(kk2, c, Kr); Ki = fmaf(-kk2, sn, Ki);
        }
        float Xr = Qr * Kr + Qi * Ki;
        float Xi = Qi * Kr - Qr * Ki;
        if (f == 0) {
            A[h][0] = Xr * (1.0f / 2048.0f);
        } else {
            A[h][2 * f - 1] =  Xr * (1.0f / 1024.0f);
            A[h][2 * f]     = -Xi * (1.0f / 1024.0f);
        }
    }
    __syncthreads();

    for (int idx = tid; idx < H_ * NC; idx += blockDim.x) {
        int h = idx / NC, kk = idx % NC;
        float m = 0.f;
#pragma unroll
        for (int hh = 0; hh < H_; hh++) m += A[hh][kk];
        m *= (1.0f / H_);
        g_C[((size_t)(b * H_ + h) * L_ + s) * NC + kk] = A[h][kk] - m;
    }
}

// ============ K1b: fp16 split coeffs gCz[bh*L+s][160] ============
__global__ void csplit_kernel() {
    size_t idx = (size_t)blockIdx.x * blockDim.x + threadIdx.x;
    if (idx >= (size_t)BH * L_ * KPZ) return;
    int c = (int)(idx % KPZ);
    size_t bs = idx / KPZ;
    int k = c % 80, part = c / 80;       // part 0 -> hi ; 1 -> lo
    __half hv = __float2half(0.f);
    if (k < NC) {
        float x = g_C[bs * NC + k];
        hv = __float2half(x);
        if (part == 1) hv = __float2half(x - __half2float(hv));
    }
    gCz[idx] = hv;
}

// ============ K2: fp16 mma corr GEMM + exp -> split-bf16 P, partial rowsum ====
// grid (16 t, 16 s, 16 bh), 256 thr, CTA 128x128, K=160 in 2 chunks of 80.
#define PCHZ 88
__global__ __launch_bounds__(256) void z_mma_kernel() {
    int bh    = blockIdx.z;
    int sbase = blockIdx.y * 128;
    int tbase = blockIdx.x * 128;

    __shared__ __align__(16) __half As[128 * PCHZ];    // 22.5 KB [s][k]
    __shared__ __align__(16) __half Bts[128 * PCHZ];   // 22.5 KB [t][k]
    __shared__ float zsh[128];

    int tid = threadIdx.x;
    int lane = tid & 31, wid = tid >> 5;
    int g = lane >> 2, tg = lane & 3;
    int mat = lane >> 3, mr = lane & 7;
    int wm = wid >> 2, wn = wid & 3;        // warp tile m64 n32

    if (tid < 128) zsh[tid] = 0.f;

    float4 acc[4][4];
#pragma unroll
    for (int i = 0; i < 4; i++)
#pragma unroll
        for (int j = 0; j < 4; j++) acc[i][j] = make_float4(0.f, 0.f, 0.f, 0.f);

    int srow = tid >> 1, spart = tid & 1;
    const __half* aG = gCz + ((size_t)bh * L_ + sbase + srow) * KPZ;
    const __half* bG = gBz + (size_t)(tbase + srow) * KPZ;

    for (int ch = 0; ch < 2; ch++) {
        __syncthreads();
#pragma unroll
        for (int j = 0; j < 5; j++) {
            int q = spart * 5 + j;                   // 10 quads = 80 halfs
            cp16g(As + srow * PCHZ + q * 8, aG + ch * 80 + q * 8);
            cp16g(Bts + srow * PCHZ + q * 8, bG + ch * 80 + q * 8);
        }
        cp_commit();
        cp_wait<0>();
        __syncthreads();

#pragma unroll
        for (int ks = 0; ks < 5; ks++) {
            int kofs = ks * 16;
            uint a[4][4], bb[4][2];
#pragma unroll
            for (int mi = 0; mi < 4; mi++) {
                int row = wm * 64 + mi * 16 + (mat & 1) * 8 + mr;
                int col = kofs + (mat >> 1) * 8;
                ldsm_x4(a[mi][0], a[mi][1], a[mi][2], a[mi][3], &As[row * PCHZ + col]);
            }
#pragma unroll
            for (int nj = 0; nj < 2; nj++) {
                int row = wn * 32 + nj * 16 + (mat >> 1) * 8 + mr;
                int col = kofs + (mat & 1) * 8;
                ldsm_x4(bb[2 * nj][0], bb[2 * nj][1], bb[2 * nj + 1][0], bb[2 * nj + 1][1],
                        &Bts[row * PCHZ + col]);
            }
#pragma unroll
            for (int mi = 0; mi < 4; mi++)
#pragma unroll
                for (int ni = 0; ni < 4; ni++)
                    mma_fp16(acc[mi][ni], a[mi][0], a[mi][1], a[mi][2], a[mi][3],
                             bb[ni][0], bb[ni][1]);
        }
    }

    // epilogue: exp, split-bf16 store, rowsum partials
    const size_t Pb = (size_t)bh * L_ * L_;
    float zl[4][2];
#pragma unroll
    for (int mi = 0; mi < 4; mi++) { zl[mi][0] = 0.f; zl[mi][1] = 0.f; }
#pragma unroll
    for (int mi = 0; mi < 4; mi++) {
        int r0 = sbase + wm * 64 + mi * 16 + g;
#pragma unroll
        for (int ni = 0; ni < 4; ni++) {
            int tc = tbase + wn * 32 + ni * 8 + 2 * tg;
            float4 c = acc[mi][ni];
            float e0 = __expf(c.x), e1 = __expf(c.y);
            float e2 = __expf(c.z), e3 = __expf(c.w);
            zl[mi][0] += e0 + e1;
            zl[mi][1] += e2 + e3;
            __nv_bfloat162 h01 = __floats2bfloat162_rn(e0, e1);
            __nv_bfloat162 h23 = __floats2bfloat162_rn(e2, e3);
            float2 hf01 = __bfloat1622float2(h01);
            float2 hf23 = __bfloat1622float2(h23);
            *(uint*)&g_Phi[Pb + (size_t)r0 * L_ + tc]       = *(uint*)&h01;
            *(uint*)&g_Phi[Pb + (size_t)(r0 + 8) * L_ + tc] = *(uint*)&h23;
            *(uint*)&g_Plo[Pb + (size_t)r0 * L_ + tc]       = pack_hi(e0 - hf01.x, e1 - hf01.y);
            *(uint*)&g_Plo[Pb + (size_t)(r0 + 8) * L_ + tc] = pack_hi(e2 - hf23.x, e3 - hf23.y);
        }
    }
#pragma unroll
    for (int mi = 0; mi < 4; mi++)
#pragma unroll
        for (int hh = 0; hh < 2; hh++) {
            float v = zl[mi][hh];
            v += __shfl_xor_sync(0xffffffffu, v, 1);
            v += __shfl_xor_sync(0xffffffffu, v, 2);
            if (tg == 0) atomicAdd(&zsh[wm * 64 + mi * 16 + g + hh * 8], v);
        }
    __syncthreads();
    if (tid < 128)
        g_Zp[((size_t)blockIdx.x * BH + bh) * L_ + sbase + tid] = zsh[tid];
}

// ============ K2b: combine partials -> invZ ============
__global__ void zcombine_kernel() {
    int i = blockIdx.x * blockDim.x + threadIdx.x;
    if (i >= BH * L_) return;
    float z = 0.f;
#pragma unroll
    for (int tt = 0; tt < 16; tt++) z += g_Zp[(size_t)tt * (BH * L_) + i];
    g_invZ[i] = 1.0f / z;
}

// ============ K3: pipelined bf16 out GEMM (unchanged from R9) ============
#define LDA3 136
#define LDV3 72
#define PBUF (32 * LDA3)
#define VBUF (32 * LDV3)
__global__ __launch_bounds__(256) void out_mma_kernel(const float* __restrict__ values) {
    int bh = blockIdx.y;
    int b  = bh >> 3, h = bh & 7;
    int lbase = blockIdx.x * 128;
    int zhalf = blockIdx.z;

    __shared__ __align__(16) char smemraw[53248];
    __nv_bfloat16* Ahi0 = (__nv_bfloat16*)smemraw;
    __nv_bfloat16* Alo0 = Ahi0 + 2 * PBUF;
    __nv_bfloat16* Vhi0 = Alo0 + 2 * PBUF;
    __nv_bfloat16* Vlo0 = Vhi0 + 2 * VBUF;
    float* osb = (float*)smemraw;

    int tid = threadIdx.x;
    int lane = tid & 31, wid = tid >> 5;
    int g = lane >> 2, tg = lane & 3;
    int mat = lane >> 3, mr = lane & 7;
    int wm = wid >> 1, wn = wid & 1;

    float4 acc[2][4];
#pragma unroll
    for (int i = 0; i < 2; i++)
#pragma unroll
        for (int j = 0; j < 4; j++) acc[i][j] = make_float4(0.f, 0.f, 0.f, 0.f);

    const size_t Pb = (size_t)bh * L_ * L_;
    const float* vptr = values + (size_t)b * L_ * E_ + h * D_;

    int psc0 = tid >> 4, pc8_0 = (tid & 15) * 8;
    int vsc = tid >> 3, vdq = tid & 7;

    {
        int sbase = zhalf * 1024;
#pragma unroll
        for (int it = 0; it < 2; it++) {
            int sc = psc0 + it * 16;
            cp16g(&Ahi0[sc * LDA3 + pc8_0], &g_Phi[Pb + (size_t)(sbase + sc) * L_ + lbase + pc8_0]);
            cp16g(&Alo0[sc * LDA3 + pc8_0], &g_Plo[Pb + (size_t)(sbase + sc) * L_ + lbase + pc8_0]);
        }
        cp_commit();
        float iz = g_invZ[bh * L_ + sbase + vsc];
#pragma unroll
        for (int j = 0; j < 2; j++) {
            int d4 = vdq + 8 * j;
            float4 v4 = *(const float4*)&vptr[(size_t)(sbase + vsc) * E_ + d4 * 4];
            v4.x *= iz; v4.y *= iz; v4.z *= iz; v4.w *= iz;
            uint h0 = pack_hi(v4.x, v4.y), h1 = pack_hi(v4.z, v4.w);
            __nv_bfloat162 b0 = *(__nv_bfloat162*)&h0;
            __nv_bfloat162 b1 = *(__nv_bfloat162*)&h1;
            float2 f0 = __bfloat1622float2(b0);
            float2 f1 = __bfloat1622float2(b1);
            *(uint2*)&Vhi0[vsc * LDV3 + d4 * 4] = make_uint2(h0, h1);
            *(uint2*)&Vlo0[vsc * LDV3 + d4 * 4] =
                make_uint2(pack_hi(v4.x - f0.x, v4.y - f0.y), pack_hi(v4.z - f1.x, v4.w - f1.y));
        }
    }

    for (int sch = 0; sch < 32; sch++) {
        int buf = sch & 1;
        float4 vr[2];
        float vizn = 0.f;
        if (sch < 31) {
            int nb = (sch + 1) & 1;
            int nsb = zhalf * 1024 + (sch + 1) * 32;
#pragma unroll
            for (int it = 0; it < 2; it++) {
                int sc = psc0 + it * 16;
                cp16g(&Ahi0[nb * PBUF + sc * LDA3 + pc8_0],
                      &g_Phi[Pb + (size_t)(nsb + sc) * L_ + lbase + pc8_0]);
                cp16g(&Alo0[nb * PBUF + sc * LDA3 + pc8_0],
                      &g_Plo[Pb + (size_t)(nsb + sc) * L_ + lbase + pc8_0]);
            }
            cp_commit();
            vizn = g_invZ[bh * L_ + nsb + vsc];
            vr[0] = *(const float4*)&vptr[(size_t)(nsb + vsc) * E_ + vdq * 4];
            vr[1] = *(const float4*)&vptr[(size_t)(nsb + vsc) * E_ + vdq * 4 + 32];
            cp_wait<1>();
        } else {
            cp_wait<0>();
        }
        __syncthreads();

        const __nv_bfloat16* Ahi = Ahi0 + buf * PBUF;
        const __nv_bfloat16* Alo = Alo0 + buf * PBUF;
        const __nv_bfloat16* Vhi = Vhi0 + buf * VBUF;
        const __nv_bfloat16* Vlo = Vlo0 + buf * VBUF;

#pragma unroll
        for (int ks = 0; ks < 2; ks++) {
            int kofs = ks * 16;
            uint ah[2][4], al[2][4], vh[4][2], vl[4][2];
            {
                int row = kofs + (mat >> 1) * 8 + mr;
#pragma unroll
                for (int mi = 0; mi < 2; mi++) {
                    int col = wm * 32 + mi * 16 + (mat & 1) * 8;
                    ldsm_x4_t(ah[mi][0], ah[mi][1], ah[mi][2], ah[mi][3], &Ahi[row * LDA3 + col]);
                    ldsm_x4_t(al[mi][0], al[mi][1], al[mi][2], al[mi][3], &Alo[row * LDA3 + col]);
                }
            }
            {
                int row = kofs + (mat & 1) * 8 + mr;
#pragma unroll
                for (int nj = 0; nj < 2; nj++) {
                    int col = wn * 32 + nj * 16 + (mat >> 1) * 8;
                    ldsm_x4_t(vh[2 * nj][0], vh[2 * nj][1], vh[2 * nj + 1][0], vh[2 * nj + 1][1],
                              &Vhi[row * LDV3 + col]);
                    ldsm_x4_t(vl[2 * nj][0], vl[2 * nj][1], vl[2 * nj + 1][0], vl[2 * nj + 1][1],
                              &Vlo[row * LDV3 + col]);
                }
            }
#pragma unroll
            for (int mi = 0; mi < 2; mi++)
#pragma unroll
                for (int ni = 0; ni < 4; ni++) {
                    mma_bf16(acc[mi][ni], ah[mi][0], ah[mi][1], ah[mi][2], ah[mi][3],
                             vh[ni][0], vh[ni][1]);
                    mma_bf16(acc[mi][ni], al[mi][0], al[mi][1], al[mi][2], al[mi][3],
                             vh[ni][0], vh[ni][1]);
                    mma_bf16(acc[mi][ni], ah[mi][0], ah[mi][1], ah[mi][2], ah[mi][3],
                             vl[ni][0], vl[ni][1]);
                }
        }

        if (sch < 31) {
            int nb = (sch + 1) & 1;
#pragma unroll
            for (int j = 0; j < 2; j++) {
                int d4 = vdq + 8 * j;
                float4 v4 = vr[j];
                v4.x *= vizn; v4.y *= vizn; v4.z *= vizn; v4.w *= vizn;
                uint h0 = pack_hi(v4.x, v4.y), h1 = pack_hi(v4.z, v4.w);
                __nv_bfloat162 b0 = *(__nv_bfloat162*)&h0;
                __nv_bfloat162 b1 = *(__nv_bfloat162*)&h1;
                float2 f0 = __bfloat1622float2(b0);
                float2 f1 = __bfloat1622float2(b1);
                *(uint2*)&Vhi0[nb * VBUF + vsc * LDV3 + d4 * 4] = make_uint2(h0, h1);
                *(uint2*)&Vlo0[nb * VBUF + vsc * LDV3 + d4 * 4] =
                    make_uint2(pack_hi(v4.x - f0.x, v4.y - f0.y),
                               pack_hi(v4.z - f1.x, v4.w - f1.y));
            }
        }
        __syncthreads();
    }

#pragma unroll
    for (int mi = 0; mi < 2; mi++) {
        int l0 = wm * 32 + mi * 16 + g;
#pragma unroll
        for (int ni = 0; ni < 4; ni++) {
            int d0 = wn * 32 + ni * 8 + 2 * tg;
            float4 c = acc[mi][ni];
            osb[l0 * 65 + d0]           = c.x;
            osb[l0 * 65 + d0 + 1]       = c.y;
            osb[(l0 + 8) * 65 + d0]     = c.z;
            osb[(l0 + 8) * 65 + d0 + 1] = c.w;
        }
    }
    __syncthreads();
    {
        int dq = tid >> 2, lq = tid & 3;
        float* op = &g_Opart[(((size_t)zhalf * BH + bh) * D_ + dq) * L_ + lbase];
#pragma unroll
        for (int j = 0; j < 8; j++) {
            int l4 = lq + 4 * j;
            float4 w;
            w.x = osb[(l4 * 4 + 0) * 65 + dq];
            w.y = osb[(l4 * 4 + 1) * 65 + dq];
            w.z = osb[(l4 * 4 + 2) * 65 + dq];
            w.w = osb[(l4 * 4 + 3) * 65 + dq];
            *(float4*)&op[l4 * 4] = w;
        }
    }
}

// ============ K3b: reduce partials + faithful scatter ============
__global__ void reduce_kernel(float* __restrict__ out) {
    int idx = blockIdx.x * blockDim.x + threadIdx.x;
    if (idx >= BH * D_ * L_) return;
    int l  = idx & (L_ - 1);
    int dd = (idx >> 11) & (D_ - 1);
    int bh = idx >> 17;
    int b  = bh >> 3, h = bh & 7;
    float v = g_Opart[idx] + g_Opart[BH * D_ * L_ + idx];
    int row = dd * 32 + h * 4 + (l >> 9);
    out[((size_t)b * 2048 + row) * 512 + (l & 511)] = v;
}

// ============ launch ============
extern "C" void kernel_launch(void* const* d_in, const int* in_sizes, int n_in,
                              void* d_out, int out_size) {
    (void)in_sizes; (void)n_in; (void)out_size;
    const float* q = (const float*)d_in[0];
    const float* k = (const float*)d_in[1];
    const float* v = (const float*)d_in[2];
    float* out = (float*)d_out;

    btsplit_kernel<<<(L_ * KPZ + 255) / 256, 256>>>();
    coeff_kernel<<<B_ * L_, 288>>>(q, k);
    csplit_kernel<<<(int)(((size_t)BH * L_ * KPZ + 255) / 256), 256>>>();
    z_mma_kernel<<<dim3(16, 16, BH), 256>>>();
    zcombine_kernel<<<(BH * L_ + 255) / 256, 256>>>();
    out_mma_kernel<<<dim3(16, BH, 2), 256>>>(v);
    reduce_kernel<<<(BH * D_ * L_ + 255) / 256, 256>>>(out);
}

// round 12
// speedup vs baseline: 1.8279x; 1.2027x over previous
#include <cuda_runtime.h>
#include <cuda_bf16.h>
#include <cuda_fp16.h>

#define B_  2
#define L_  2048
#define E_  512
#define H_  8
#define D_  64
#define NC  65
#define KPZ 80         // fp16 single-term K for K2: [C 65 | pad 15]
#define BH  (B_*H_)

typedef unsigned int uint;

// -------- scratch --------
__device__ float g_C[(size_t)BH * L_ * NC];
__device__ __half gCz[(size_t)BH * L_ * KPZ];           // 5.2 MB [bh*L+s][80]
__device__ __half gBz[L_ * KPZ];                        // 0.33 MB [t][80]
__device__ float g_Zp[16 * BH * L_];
__device__ float g_invZ[BH * L_];
__device__ __nv_bfloat16 g_Phi[(size_t)BH * L_ * L_];   // 134 MB [bh][s][t]
__device__ __nv_bfloat16 g_Plo[(size_t)BH * L_ * L_];   // 134 MB
__device__ float g_Opart[2 * BH * D_ * L_];             // 16 MB  [z][bh][d][l]

// ---------------- helpers ----------------
__device__ __forceinline__ uint smem_u32(const void* p) {
    uint a;
    asm("{ .reg .u64 t; cvta.to.shared.u64 t, %1; cvt.u32.u64 %0, t; }" : "=r"(a) : "l"(p));
    return a;
}
__device__ __forceinline__ void mma_bf16(float4& c,
                                         uint a0, uint a1, uint a2, uint a3,
                                         uint b0, uint b1) {
    asm volatile(
        "mma.sync.aligned.m16n8k16.row.col.f32.bf16.bf16.f32 "
        "{%0,%1,%2,%3}, {%4,%5,%6,%7}, {%8,%9}, {%0,%1,%2,%3};"
        : "+f"(c.x), "+f"(c.y), "+f"(c.z), "+f"(c.w)
        : "r"(a0), "r"(a1), "r"(a2), "r"(a3), "r"(b0), "r"(b1));
}
__device__ __forceinline__ void mma_fp16(float4& c,
                                         uint a0, uint a1, uint a2, uint a3,
                                         uint b0, uint b1) {
    asm volatile(
        "mma.sync.aligned.m16n8k16.row.col.f32.f16.f16.f32 "
        "{%0,%1,%2,%3}, {%4,%5,%6,%7}, {%8,%9}, {%0,%1,%2,%3};"
        : "+f"(c.x), "+f"(c.y), "+f"(c.z), "+f"(c.w)
        : "r"(a0), "r"(a1), "r"(a2), "r"(a3), "r"(b0), "r"(b1));
}
__device__ __forceinline__ void ldsm_x4(uint& r0, uint& r1, uint& r2, uint& r3,
                                        const void* p) {
    uint a = smem_u32(p);
    asm volatile("ldmatrix.sync.aligned.m8n8.x4.shared.b16 {%0,%1,%2,%3}, [%4];"
                 : "=r"(r0), "=r"(r1), "=r"(r2), "=r"(r3) : "r"(a));
}
__device__ __forceinline__ void ldsm_x4_t(uint& r0, uint& r1, uint& r2, uint& r3,
                                          const void* p) {
    uint a = smem_u32(p);
    asm volatile("ldmatrix.sync.aligned.m8n8.x4.trans.shared.b16 {%0,%1,%2,%3}, [%4];"
                 : "=r"(r0), "=r"(r1), "=r"(r2), "=r"(r3) : "r"(a));
}
__device__ __forceinline__ uint pack_hi(float x, float y) {
    __nv_bfloat162 h = __floats2bfloat162_rn(x, y);
    return *(uint*)&h;
}
__device__ __forceinline__ void cp16g(void* smem, const void* gmem) {
    uint a = smem_u32(smem);
    asm volatile("cp.async.cg.shared.global [%0], [%1], 16;" :: "r"(a), "l"(gmem));
}
__device__ __forceinline__ void cp_commit() { asm volatile("cp.async.commit_group;"); }
template <int N> __device__ __forceinline__ void cp_wait() {
    asm volatile("cp.async.wait_group %0;" :: "n"(N));
}

// ============ K0: fp16 basis gBz[t][80] ============
__global__ void btsplit_kernel() {
    int idx = blockIdx.x * blockDim.x + threadIdx.x;
    if (idx >= L_ * KPZ) return;
    int k = idx % KPZ, t = idx / KPZ;
    float v = 0.f;
    if (k == 0) v = 1.0f;
    else if (k < NC) {
        int f = (k + 1) >> 1;
        int ph = (f * t) & (L_ - 1);
        float s, c;
        sincospif((float)ph * (1.0f / 1024.0f), &s, &c);
        v = (k & 1) ? c : s;
    }
    gBz[idx] = __float2half(v);
}

// ============ K1: 64-pt DFTs -> coeffs, head-mean subtracted ============
__global__ __launch_bounds__(288) void coeff_kernel(const float* __restrict__ q,
                                                    const float* __restrict__ kin) {
    int bs = blockIdx.x;
    int b  = bs >> 11;
    int s  = bs & (L_ - 1);

    __shared__ float sq[E_], sk[E_];
    __shared__ float twc[64], tws[64];
    __shared__ float A[H_][NC];

    int tid = threadIdx.x;
    for (int i = tid; i < E_; i += blockDim.x) {
        sq[i] = q[(size_t)bs * E_ + i];
        sk[i] = kin[(size_t)bs * E_ + i];
    }
    if (tid < 64) {
        float ss, cc;
        sincospif((float)tid * (1.0f / 32.0f), &ss, &cc);
        twc[tid] = cc; tws[tid] = ss;
    }
    __syncthreads();

    if (tid < H_ * 33) {
        int h = tid / 33, f = tid % 33;
        const float* qh = sq + h * D_;
        const float* kh = sk + h * D_;
        float Qr = 0.f, Qi = 0.f, Kr = 0.f, Ki = 0.f;
#pragma unroll 8
        for (int j = 0; j < 64; j++) {
            int m = (f * j) & 63;
            float c = twc[m], sn = tws[m];
            float qq = qh[j], kk2 = kh[j];
            Qr = fmaf(qq, c, Qr);  Qi = fmaf(-qq, sn, Qi);
            Kr = fmaf(kk2, c, Kr); Ki = fmaf(-kk2, sn, Ki);
        }
        float Xr = Qr * Kr + Qi * Ki;
        float Xi = Qi * Kr - Qr * Ki;
        if (f == 0) {
            A[h][0] = Xr * (1.0f / 2048.0f);
        } else {
            A[h][2 * f - 1] =  Xr * (1.0f / 1024.0f);
            A[h][2 * f]     = -Xi * (1.0f / 1024.0f);
        }
    }
    __syncthreads();

    for (int idx = tid; idx < H_ * NC; idx += blockDim.x) {
        int h = idx / NC, kk = idx % NC;
        float m = 0.f;
#pragma unroll
        for (int hh = 0; hh < H_; hh++) m += A[hh][kk];
        m *= (1.0f / H_);
        g_C[((size_t)(b * H_ + h) * L_ + s) * NC + kk] = A[h][kk] - m;
    }
}

// ============ K1b: fp16 coeffs gCz[bh*L+s][80] ============
__global__ void csplit_kernel() {
    size_t idx = (size_t)blockIdx.x * blockDim.x + threadIdx.x;
    if (idx >= (size_t)BH * L_ * KPZ) return;
    int k = (int)(idx % KPZ);
    size_t bs = idx / KPZ;
    __half hv = __float2half(0.f);
    if (k < NC) hv = __float2half(g_C[bs * NC + k]);
    gCz[idx] = hv;
}

// ============ K2: fp16 mma corr GEMM + exp -> split-bf16 P, partial rowsum ====
// grid (16 t, 16 s, 16 bh), 256 thr, CTA 128x128, single K chunk of 80.
#define PCHZ 88
__global__ __launch_bounds__(256) void z_mma_kernel() {
    int bh    = blockIdx.z;
    int sbase = blockIdx.y * 128;
    int tbase = blockIdx.x * 128;

    __shared__ __align__(16) __half As[128 * PCHZ];    // 22.5 KB [s][k]
    __shared__ __align__(16) __half Bts[128 * PCHZ];   // 22.5 KB [t][k]
    __shared__ float zsh[128];

    int tid = threadIdx.x;
    int lane = tid & 31, wid = tid >> 5;
    int g = lane >> 2, tg = lane & 3;
    int mat = lane >> 3, mr = lane & 7;
    int wm = wid >> 2, wn = wid & 3;        // warp tile m64 n32

    if (tid < 128) zsh[tid] = 0.f;

    float4 acc[4][4];
#pragma unroll
    for (int i = 0; i < 4; i++)
#pragma unroll
        for (int j = 0; j < 4; j++) acc[i][j] = make_float4(0.f, 0.f, 0.f, 0.f);

    int srow = tid >> 1, spart = tid & 1;
    const __half* aG = gCz + ((size_t)bh * L_ + sbase + srow) * KPZ;
    const __half* bG = gBz + (size_t)(tbase + srow) * KPZ;

    // stage the single K=80 chunk
#pragma unroll
    for (int j = 0; j < 5; j++) {
        int q = spart * 5 + j;                   // 10 quads = 80 halfs
        cp16g(As + srow * PCHZ + q * 8, aG + q * 8);
        cp16g(Bts + srow * PCHZ + q * 8, bG + q * 8);
    }
    cp_commit();
    cp_wait<0>();
    __syncthreads();

#pragma unroll
    for (int ks = 0; ks < 5; ks++) {
        int kofs = ks * 16;
        uint a[4][4], bb[4][2];
#pragma unroll
        for (int mi = 0; mi < 4; mi++) {
            int row = wm * 64 + mi * 16 + (mat & 1) * 8 + mr;
            int col = kofs + (mat >> 1) * 8;
            ldsm_x4(a[mi][0], a[mi][1], a[mi][2], a[mi][3], &As[row * PCHZ + col]);
        }
#pragma unroll
        for (int nj = 0; nj < 2; nj++) {
            int row = wn * 32 + nj * 16 + (mat >> 1) * 8 + mr;
            int col = kofs + (mat & 1) * 8;
            ldsm_x4(bb[2 * nj][0], bb[2 * nj][1], bb[2 * nj + 1][0], bb[2 * nj + 1][1],
                    &Bts[row * PCHZ + col]);
        }
#pragma unroll
        for (int mi = 0; mi < 4; mi++)
#pragma unroll
            for (int ni = 0; ni < 4; ni++)
                mma_fp16(acc[mi][ni], a[mi][0], a[mi][1], a[mi][2], a[mi][3],
                         bb[ni][0], bb[ni][1]);
    }

    // epilogue: exp, split-bf16 store, rowsum partials
    const size_t Pb = (size_t)bh * L_ * L_;
    float zl[4][2];
#pragma unroll
    for (int mi = 0; mi < 4; mi++) { zl[mi][0] = 0.f; zl[mi][1] = 0.f; }
#pragma unroll
    for (int mi = 0; mi < 4; mi++) {
        int r0 = sbase + wm * 64 + mi * 16 + g;
#pragma unroll
        for (int ni = 0; ni < 4; ni++) {
            int tc = tbase + wn * 32 + ni * 8 + 2 * tg;
            float4 c = acc[mi][ni];
            float e0 = __expf(c.x), e1 = __expf(c.y);
            float e2 = __expf(c.z), e3 = __expf(c.w);
            zl[mi][0] += e0 + e1;
            zl[mi][1] += e2 + e3;
            __nv_bfloat162 h01 = __floats2bfloat162_rn(e0, e1);
            __nv_bfloat162 h23 = __floats2bfloat162_rn(e2, e3);
            float2 hf01 = __bfloat1622float2(h01);
            float2 hf23 = __bfloat1622float2(h23);
            *(uint*)&g_Phi[Pb + (size_t)r0 * L_ + tc]       = *(uint*)&h01;
            *(uint*)&g_Phi[Pb + (size_t)(r0 + 8) * L_ + tc] = *(uint*)&h23;
            *(uint*)&g_Plo[Pb + (size_t)r0 * L_ + tc]       = pack_hi(e0 - hf01.x, e1 - hf01.y);
            *(uint*)&g_Plo[Pb + (size_t)(r0 + 8) * L_ + tc] = pack_hi(e2 - hf23.x, e3 - hf23.y);
        }
    }
#pragma unroll
    for (int mi = 0; mi < 4; mi++)
#pragma unroll
        for (int hh = 0; hh < 2; hh++) {
            float v = zl[mi][hh];
            v += __shfl_xor_sync(0xffffffffu, v, 1);
            v += __shfl_xor_sync(0xffffffffu, v, 2);
            if (tg == 0) atomicAdd(&zsh[wm * 64 + mi * 16 + g + hh * 8], v);
        }
    __syncthreads();
    if (tid < 128)
        g_Zp[((size_t)blockIdx.x * BH + bh) * L_ + sbase + tid] = zsh[tid];
}

// ============ K2b: combine partials -> invZ ============
__global__ void zcombine_kernel() {
    int i = blockIdx.x * blockDim.x + threadIdx.x;
    if (i >= BH * L_) return;
    float z = 0.f;
#pragma unroll
    for (int tt = 0; tt < 16; tt++) z += g_Zp[(size_t)tt * (BH * L_) + i];
    g_invZ[i] = 1.0f / z;
}

// ============ K3: pipelined bf16 out GEMM (unchanged) ============
#define LDA3 136
#define LDV3 72
#define PBUF (32 * LDA3)
#define VBUF (32 * LDV3)
__global__ __launch_bounds__(256) void out_mma_kernel(const float* __restrict__ values) {
    int bh = blockIdx.y;
    int b  = bh >> 3, h = bh & 7;
    int lbase = blockIdx.x * 128;
    int zhalf = blockIdx.z;

    __shared__ __align__(16) char smemraw[53248];
    __nv_bfloat16* Ahi0 = (__nv_bfloat16*)smemraw;
    __nv_bfloat16* Alo0 = Ahi0 + 2 * PBUF;
    __nv_bfloat16* Vhi0 = Alo0 + 2 * PBUF;
    __nv_bfloat16* Vlo0 = Vhi0 + 2 * VBUF;
    float* osb = (float*)smemraw;

    int tid = threadIdx.x;
    int lane = tid & 31, wid = tid >> 5;
    int g = lane >> 2, tg = lane & 3;
    int mat = lane >> 3, mr = lane & 7;
    int wm = wid >> 1, wn = wid & 1;

    float4 acc[2][4];
#pragma unroll
    for (int i = 0; i < 2; i++)
#pragma unroll
        for (int j = 0; j < 4; j++) acc[i][j] = make_float4(0.f, 0.f, 0.f, 0.f);

    const size_t Pb = (size_t)bh * L_ * L_;
    const float* vptr = values + (size_t)b * L_ * E_ + h * D_;

    int psc0 = tid >> 4, pc8_0 = (tid & 15) * 8;
    int vsc = tid >> 3, vdq = tid & 7;

    {
        int sbase = zhalf * 1024;
#pragma unroll
        for (int it = 0; it < 2; it++) {
            int sc = psc0 + it * 16;
            cp16g(&Ahi0[sc * LDA3 + pc8_0], &g_Phi[Pb + (size_t)(sbase + sc) * L_ + lbase + pc8_0]);
            cp16g(&Alo0[sc * LDA3 + pc8_0], &g_Plo[Pb + (size_t)(sbase + sc) * L_ + lbase + pc8_0]);
        }
        cp_commit();
        float iz = g_invZ[bh * L_ + sbase + vsc];
#pragma unroll
        for (int j = 0; j < 2; j++) {
            int d4 = vdq + 8 * j;
            float4 v4 = *(const float4*)&vptr[(size_t)(sbase + vsc) * E_ + d4 * 4];
            v4.x *= iz; v4.y *= iz; v4.z *= iz; v4.w *= iz;
            uint h0 = pack_hi(v4.x, v4.y), h1 = pack_hi(v4.z, v4.w);
            __nv_bfloat162 b0 = *(__nv_bfloat162*)&h0;
            __nv_bfloat162 b1 = *(__nv_bfloat162*)&h1;
            float2 f0 = __bfloat1622float2(b0);
            float2 f1 = __bfloat1622float2(b1);
            *(uint2*)&Vhi0[vsc * LDV3 + d4 * 4] = make_uint2(h0, h1);
            *(uint2*)&Vlo0[vsc * LDV3 + d4 * 4] =
                make_uint2(pack_hi(v4.x - f0.x, v4.y - f0.y), pack_hi(v4.z - f1.x, v4.w - f1.y));
        }
    }

    for (int sch = 0; sch < 32; sch++) {
        int buf = sch & 1;
        float4 vr[2];
        float vizn = 0.f;
        if (sch < 31) {
            int nb = (sch + 1) & 1;
            int nsb = zhalf * 1024 + (sch + 1) * 32;
#pragma unroll
            for (int it = 0; it < 2; it++) {
                int sc = psc0 + it * 16;
                cp16g(&Ahi0[nb * PBUF + sc * LDA3 + pc8_0],
                      &g_Phi[Pb + (size_t)(nsb + sc) * L_ + lbase + pc8_0]);
                cp16g(&Alo0[nb * PBUF + sc * LDA3 + pc8_0],
                      &g_Plo[Pb + (size_t)(nsb + sc) * L_ + lbase + pc8_0]);
            }
            cp_commit();
            vizn = g_invZ[bh * L_ + nsb + vsc];
            vr[0] = *(const float4*)&vptr[(size_t)(nsb + vsc) * E_ + vdq * 4];
            vr[1] = *(const float4*)&vptr[(size_t)(nsb + vsc) * E_ + vdq * 4 + 32];
            cp_wait<1>();
        } else {
            cp_wait<0>();
        }
        __syncthreads();

        const __nv_bfloat16* Ahi = Ahi0 + buf * PBUF;
        const __nv_bfloat16* Alo = Alo0 + buf * PBUF;
        const __nv_bfloat16* Vhi = Vhi0 + buf * VBUF;
        const __nv_bfloat16* Vlo = Vlo0 + buf * VBUF;

#pragma unroll
        for (int ks = 0; ks < 2; ks++) {
            int kofs = ks * 16;
            uint ah[2][4], al[2][4], vh[4][2], vl[4][2];
            {
                int row = kofs + (mat >> 1) * 8 + mr;
#pragma unroll
                for (int mi = 0; mi < 2; mi++) {
                    int col = wm * 32 + mi * 16 + (mat & 1) * 8;
                    ldsm_x4_t(ah[mi][0], ah[mi][1], ah[mi][2], ah[mi][3], &Ahi[row * LDA3 + col]);
                    ldsm_x4_t(al[mi][0], al[mi][1], al[mi][2], al[mi][3], &Alo[row * LDA3 + col]);
                }
            }
            {
                int row = kofs + (mat & 1) * 8 + mr;
#pragma unroll
                for (int nj = 0; nj < 2; nj++) {
                    int col = wn * 32 + nj * 16 + (mat >> 1) * 8;
                    ldsm_x4_t(vh[2 * nj][0], vh[2 * nj][1], vh[2 * nj + 1][0], vh[2 * nj + 1][1],
                              &Vhi[row * LDV3 + col]);
                    ldsm_x4_t(vl[2 * nj][0], vl[2 * nj][1], vl[2 * nj + 1][0], vl[2 * nj + 1][1],
                              &Vlo[row * LDV3 + col]);
                }
            }
#pragma unroll
            for (int mi = 0; mi < 2; mi++)
#pragma unroll
                for (int ni = 0; ni < 4; ni++) {
                    mma_bf16(acc[mi][ni], ah[mi][0], ah[mi][1], ah[mi][2], ah[mi][3],
                             vh[ni][0], vh[ni][1]);
                    mma_bf16(acc[mi][ni], al[mi][0], al[mi][1], al[mi][2], al[mi][3],
                             vh[ni][0], vh[ni][1]);
                    mma_bf16(acc[mi][ni], ah[mi][0], ah[mi][1], ah[mi][2], ah[mi][3],
                             vl[ni][0], vl[ni][1]);
                }
        }

        if (sch < 31) {
            int nb = (sch + 1) & 1;
#pragma unroll
            for (int j = 0; j < 2; j++) {
                int d4 = vdq + 8 * j;
                float4 v4 = vr[j];
                v4.x *= vizn; v4.y *= vizn; v4.z *= vizn; v4.w *= vizn;
                uint h0 = pack_hi(v4.x, v4.y), h1 = pack_hi(v4.z, v4.w);
                __nv_bfloat162 b0 = *(__nv_bfloat162*)&h0;
                __nv_bfloat162 b1 = *(__nv_bfloat162*)&h1;
                float2 f0 = __bfloat1622float2(b0);
                float2 f1 = __bfloat1622float2(b1);
                *(uint2*)&Vhi0[nb * VBUF + vsc * LDV3 + d4 * 4] = make_uint2(h0, h1);
                *(uint2*)&Vlo0[nb * VBUF + vsc * LDV3 + d4 * 4] =
                    make_uint2(pack_hi(v4.x - f0.x, v4.y - f0.y),
                               pack_hi(v4.z - f1.x, v4.w - f1.y));
            }
        }
        __syncthreads();
    }

#pragma unroll
    for (int mi = 0; mi < 2; mi++) {
        int l0 = wm * 32 + mi * 16 + g;
#pragma unroll
        for (int ni = 0; ni < 4; ni++) {
            int d0 = wn * 32 + ni * 8 + 2 * tg;
            float4 c = acc[mi][ni];
            osb[l0 * 65 + d0]           = c.x;
            osb[l0 * 65 + d0 + 1]       = c.y;
            osb[(l0 + 8) * 65 + d0]     = c.z;
            osb[(l0 + 8) * 65 + d0 + 1] = c.w;
        }
    }
    __syncthreads();
    {
        int dq = tid >> 2, lq = tid & 3;
        float* op = &g_Opart[(((size_t)zhalf * BH + bh) * D_ + dq) * L_ + lbase];
#pragma unroll
        for (int j = 0; j < 8; j++) {
            int l4 = lq + 4 * j;
            float4 w;
            w.x = osb[(l4 * 4 + 0) * 65 + dq];
            w.y = osb[(l4 * 4 + 1) * 65 + dq];
            w.z = osb[(l4 * 4 + 2) * 65 + dq];
            w.w = osb[(l4 * 4 + 3) * 65 + dq];
            *(float4*)&op[l4 * 4] = w;
        }
    }
}

// ============ K3b: reduce partials + faithful scatter ============
__global__ void reduce_kernel(float* __restrict__ out) {
    int idx = blockIdx.x * blockDim.x + threadIdx.x;
    if (idx >= BH * D_ * L_) return;
    int l  = idx & (L_ - 1);
    int dd = (idx >> 11) & (D_ - 1);
    int bh = idx >> 17;
    int b  = bh >> 3, h = bh & 7;
    float v = g_Opart[idx] + g_Opart[BH * D_ * L_ + idx];
    int row = dd * 32 + h * 4 + (l >> 9);
    out[((size_t)b * 2048 + row) * 512 + (l & 511)] = v;
}

// ============ launch ============
extern "C" void kernel_launch(void* const* d_in, const int* in_sizes, int n_in,
                              void* d_out, int out_size) {
    (void)in_sizes; (void)n_in; (void)out_size;
    const float* q = (const float*)d_in[0];
    const float* k = (const float*)d_in[1];
    const float* v = (const float*)d_in[2];
    float* out = (float*)d_out;

    btsplit_kernel<<<(L_ * KPZ + 255) / 256, 256>>>();
    coeff_kernel<<<B_ * L_, 288>>>(q, k);
    csplit_kernel<<<(int)(((size_t)BH * L_ * KPZ + 255) / 256), 256>>>();
    z_mma_kernel<<<dim3(16, 16, BH), 256>>>();
    zcombine_kernel<<<(BH * L_ + 255) / 256, 256>>>();
    out_mma_kernel<<<dim3(16, BH, 2), 256>>>(v);
    reduce_kernel<<<(BH * D_ * L_ + 255) / 256, 256>>>(out);
}

// round 13
// speedup vs baseline: 2.1899x; 1.1980x over previous
#include <cuda_runtime.h>
#include <cuda_fp16.h>

#define B_  2
#define L_  2048
#define E_  512
#define H_  8
#define D_  64
#define NC  65
#define KPZ 80         // fp16 K for corr GEMM: [C 65 | pad 15]
#define BH  (B_*H_)

typedef unsigned int uint;

// -------- scratch --------
__device__ float g_C[(size_t)BH * L_ * NC];
__device__ __half gCz[(size_t)BH * L_ * KPZ];           // 5.2 MB [bh*L+s][80]
__device__ __half gBz[L_ * KPZ];                        // 0.33 MB [t][80]
__device__ float g_Zp[16 * BH * L_];                    // partial sums (tile-normed)
__device__ float g_E[16 * BH * L_];                     // per (ttile,row) max
__device__ float g_invZ[BH * L_];
__device__ __half g_Pf[(size_t)BH * L_ * L_];           // 134 MB [bh][s][t], exp(c-m)
__device__ float g_Opart[2 * BH * D_ * L_];             // 16 MB  [z][bh][d][l]

// ---------------- helpers ----------------
__device__ __forceinline__ uint smem_u32(const void* p) {
    uint a;
    asm("{ .reg .u64 t; cvta.to.shared.u64 t, %1; cvt.u32.u64 %0, t; }" : "=r"(a) : "l"(p));
    return a;
}
__device__ __forceinline__ void mma_fp16(float4& c,
                                         uint a0, uint a1, uint a2, uint a3,
                                         uint b0, uint b1) {
    asm volatile(
        "mma.sync.aligned.m16n8k16.row.col.f32.f16.f16.f32 "
        "{%0,%1,%2,%3}, {%4,%5,%6,%7}, {%8,%9}, {%0,%1,%2,%3};"
        : "+f"(c.x), "+f"(c.y), "+f"(c.z), "+f"(c.w)
        : "r"(a0), "r"(a1), "r"(a2), "r"(a3), "r"(b0), "r"(b1));
}
__device__ __forceinline__ void ldsm_x4(uint& r0, uint& r1, uint& r2, uint& r3,
                                        const void* p) {
    uint a = smem_u32(p);
    asm volatile("ldmatrix.sync.aligned.m8n8.x4.shared.b16 {%0,%1,%2,%3}, [%4];"
                 : "=r"(r0), "=r"(r1), "=r"(r2), "=r"(r3) : "r"(a));
}
__device__ __forceinline__ void ldsm_x4_t(uint& r0, uint& r1, uint& r2, uint& r3,
                                          const void* p) {
    uint a = smem_u32(p);
    asm volatile("ldmatrix.sync.aligned.m8n8.x4.trans.shared.b16 {%0,%1,%2,%3}, [%4];"
                 : "=r"(r0), "=r"(r1), "=r"(r2), "=r"(r3) : "r"(a));
}
__device__ __forceinline__ uint pack_h2(float x, float y) {
    __half2 h = __floats2half2_rn(x, y);
    return *(uint*)&h;
}
__device__ __forceinline__ void cp16g(void* smem, const void* gmem) {
    uint a = smem_u32(smem);
    asm volatile("cp.async.cg.shared.global [%0], [%1], 16;" :: "r"(a), "l"(gmem));
}
__device__ __forceinline__ void cp_commit() { asm volatile("cp.async.commit_group;"); }
template <int N> __device__ __forceinline__ void cp_wait() {
    asm volatile("cp.async.wait_group %0;" :: "n"(N));
}

// ============ K0: fp16 basis gBz[t][80] ============
__global__ void btsplit_kernel() {
    int idx = blockIdx.x * blockDim.x + threadIdx.x;
    if (idx >= L_ * KPZ) return;
    int k = idx % KPZ, t = idx / KPZ;
    float v = 0.f;
    if (k == 0) v = 1.0f;
    else if (k < NC) {
        int f = (k + 1) >> 1;
        int ph = (f * t) & (L_ - 1);
        float s, c;
        sincospif((float)ph * (1.0f / 1024.0f), &s, &c);
        v = (k & 1) ? c : s;
    }
    gBz[idx] = __float2half(v);
}

// ============ K1: 64-pt DFTs -> coeffs, head-mean subtracted ============
__global__ __launch_bounds__(288) void coeff_kernel(const float* __restrict__ q,
                                                    const float* __restrict__ kin) {
    int bs = blockIdx.x;
    int b  = bs >> 11;
    int s  = bs & (L_ - 1);

    __shared__ float sq[E_], sk[E_];
    __shared__ float twc[64], tws[64];
    __shared__ float A[H_][NC];

    int tid = threadIdx.x;
    for (int i = tid; i < E_; i += blockDim.x) {
        sq[i] = q[(size_t)bs * E_ + i];
        sk[i] = kin[(size_t)bs * E_ + i];
    }
    if (tid < 64) {
        float ss, cc;
        sincospif((float)tid * (1.0f / 32.0f), &ss, &cc);
        twc[tid] = cc; tws[tid] = ss;
    }
    __syncthreads();

    if (tid < H_ * 33) {
        int h = tid / 33, f = tid % 33;
        const float* qh = sq + h * D_;
        const float* kh = sk + h * D_;
        float Qr = 0.f, Qi = 0.f, Kr = 0.f, Ki = 0.f;
#pragma unroll 8
        for (int j = 0; j < 64; j++) {
            int m = (f * j) & 63;
            float c = twc[m], sn = tws[m];
            float qq = qh[j], kk2 = kh[j];
            Qr = fmaf(qq, c, Qr);  Qi = fmaf(-qq, sn, Qi);
            Kr = fmaf(kk2, c, Kr); Ki = fmaf(-kk2, sn, Ki);
        }
        float Xr = Qr * Kr + Qi * Ki;
        float Xi = Qi * Kr - Qr * Ki;
        if (f == 0) {
            A[h][0] = Xr * (1.0f / 2048.0f);
        } else {
            A[h][2 * f - 1] =  Xr * (1.0f / 1024.0f);
            A[h][2 * f]     = -Xi * (1.0f / 1024.0f);
        }
    }
    __syncthreads();

    for (int idx = tid; idx < H_ * NC; idx += blockDim.x) {
        int h = idx / NC, kk = idx % NC;
        float m = 0.f;
#pragma unroll
        for (int hh = 0; hh < H_; hh++) m += A[hh][kk];
        m *= (1.0f / H_);
        g_C[((size_t)(b * H_ + h) * L_ + s) * NC + kk] = A[h][kk] - m;
    }
}

// ============ K1b: fp16 coeffs gCz[bh*L+s][80] ============
__global__ void csplit_kernel() {
    size_t idx = (size_t)blockIdx.x * blockDim.x + threadIdx.x;
    if (idx >= (size_t)BH * L_ * KPZ) return;
    int k = (int)(idx % KPZ);
    size_t bs = idx / KPZ;
    __half hv = __float2half(0.f);
    if (k < NC) hv = __float2half(g_C[bs * NC + k]);
    gCz[idx] = hv;
}

// ============ K2: fp16 mma corr GEMM + tile-softmax -> fp16 P, E, Zp ========
// grid (16 t, 16 s, 16 bh), 256 thr, CTA 128x128, single K chunk of 80.
#define PCHZ 88
__global__ __launch_bounds__(256) void z_mma_kernel() {
    int bh    = blockIdx.z;
    int sbase = blockIdx.y * 128;
    int tbase = blockIdx.x * 128;

    __shared__ __align__(16) __half As[128 * PCHZ];    // 22.5 KB [s][k]
    __shared__ __align__(16) __half Bts[128 * PCHZ];   // 22.5 KB [t][k]
    __shared__ float rmx[128][5];
    __shared__ float zsh[128];

    int tid = threadIdx.x;
    int lane = tid & 31, wid = tid >> 5;
    int g = lane >> 2, tg = lane & 3;
    int mat = lane >> 3, mr = lane & 7;
    int wm = wid >> 2, wn = wid & 3;        // warp tile m64 n32

    if (tid < 128) zsh[tid] = 0.f;

    float4 acc[4][4];
#pragma unroll
    for (int i = 0; i < 4; i++)
#pragma unroll
        for (int j = 0; j < 4; j++) acc[i][j] = make_float4(0.f, 0.f, 0.f, 0.f);

    int srow = tid >> 1, spart = tid & 1;
    const __half* aG = gCz + ((size_t)bh * L_ + sbase + srow) * KPZ;
    const __half* bG = gBz + (size_t)(tbase + srow) * KPZ;

#pragma unroll
    for (int j = 0; j < 5; j++) {
        int q = spart * 5 + j;
        cp16g(As + srow * PCHZ + q * 8, aG + q * 8);
        cp16g(Bts + srow * PCHZ + q * 8, bG + q * 8);
    }
    cp_commit();
    cp_wait<0>();
    __syncthreads();

#pragma unroll
    for (int ks = 0; ks < 5; ks++) {
        int kofs = ks * 16;
        uint a[4][4], bb[4][2];
#pragma unroll
        for (int mi = 0; mi < 4; mi++) {
            int row = wm * 64 + mi * 16 + (mat & 1) * 8 + mr;
            int col = kofs + (mat >> 1) * 8;
            ldsm_x4(a[mi][0], a[mi][1], a[mi][2], a[mi][3], &As[row * PCHZ + col]);
        }
#pragma unroll
        for (int nj = 0; nj < 2; nj++) {
            int row = wn * 32 + nj * 16 + (mat >> 1) * 8 + mr;
            int col = kofs + (mat & 1) * 8;
            ldsm_x4(bb[2 * nj][0], bb[2 * nj][1], bb[2 * nj + 1][0], bb[2 * nj + 1][1],
                    &Bts[row * PCHZ + col]);
        }
#pragma unroll
        for (int mi = 0; mi < 4; mi++)
#pragma unroll
            for (int ni = 0; ni < 4; ni++)
                mma_fp16(acc[mi][ni], a[mi][0], a[mi][1], a[mi][2], a[mi][3],
                         bb[ni][0], bb[ni][1]);
    }

    // ---- epilogue: per-(row,tile) max -> exp(c-m) fp16 store + Zp + E ----
#pragma unroll
    for (int mi = 0; mi < 4; mi++) {
        float m0 = -1e30f, m1 = -1e30f;
#pragma unroll
        for (int ni = 0; ni < 4; ni++) {
            float4 c = acc[mi][ni];
            m0 = fmaxf(m0, fmaxf(c.x, c.y));
            m1 = fmaxf(m1, fmaxf(c.z, c.w));
        }
        m0 = fmaxf(m0, __shfl_xor_sync(0xffffffffu, m0, 1));
        m0 = fmaxf(m0, __shfl_xor_sync(0xffffffffu, m0, 2));
        m1 = fmaxf(m1, __shfl_xor_sync(0xffffffffu, m1, 1));
        m1 = fmaxf(m1, __shfl_xor_sync(0xffffffffu, m1, 2));
        if (tg == 0) {
            rmx[wm * 64 + mi * 16 + g][wn]     = m0;
            rmx[wm * 64 + mi * 16 + g + 8][wn] = m1;
        }
    }
    __syncthreads();
    if (tid < 128) {
        float mm = fmaxf(fmaxf(rmx[tid][0], rmx[tid][1]), fmaxf(rmx[tid][2], rmx[tid][3]));
        rmx[tid][4] = mm;
        g_E[((size_t)blockIdx.x * BH + bh) * L_ + sbase + tid] = mm;
    }
    __syncthreads();

    const size_t Pb = (size_t)bh * L_ * L_;
    float zl[4][2];
#pragma unroll
    for (int mi = 0; mi < 4; mi++) { zl[mi][0] = 0.f; zl[mi][1] = 0.f; }
#pragma unroll
    for (int mi = 0; mi < 4; mi++) {
        int lr0 = wm * 64 + mi * 16 + g;
        float mA = rmx[lr0][4], mB = rmx[lr0 + 8][4];
        int r0 = sbase + lr0;
#pragma unroll
        for (int ni = 0; ni < 4; ni++) {
            int tc = tbase + wn * 32 + ni * 8 + 2 * tg;
            float4 c = acc[mi][ni];
            float e0 = __expf(c.x - mA), e1 = __expf(c.y - mA);
            float e2 = __expf(c.z - mB), e3 = __expf(c.w - mB);
            zl[mi][0] += e0 + e1;
            zl[mi][1] += e2 + e3;
            *(uint*)&g_Pf[Pb + (size_t)r0 * L_ + tc]       = pack_h2(e0, e1);
            *(uint*)&g_Pf[Pb + (size_t)(r0 + 8) * L_ + tc] = pack_h2(e2, e3);
        }
    }
#pragma unroll
    for (int mi = 0; mi < 4; mi++)
#pragma unroll
        for (int hh = 0; hh < 2; hh++) {
            float v = zl[mi][hh];
            v += __shfl_xor_sync(0xffffffffu, v, 1);
            v += __shfl_xor_sync(0xffffffffu, v, 2);
            if (tg == 0) atomicAdd(&zsh[wm * 64 + mi * 16 + g + hh * 8], v);
        }
    __syncthreads();
    if (tid < 128)
        g_Zp[((size_t)blockIdx.x * BH + bh) * L_ + sbase + tid] = zsh[tid];
}

// ============ K2b: Z = sum_tt e^E * Zp -> invZ ============
__global__ void zcombine_kernel() {
    int i = blockIdx.x * blockDim.x + threadIdx.x;
    if (i >= BH * L_) return;
    float z = 0.f;
#pragma unroll
    for (int tt = 0; tt < 16; tt++)
        z += __expf(g_E[(size_t)tt * (BH * L_) + i]) * g_Zp[(size_t)tt * (BH * L_) + i];
    g_invZ[i] = 1.0f / z;
}

// ============ K3: single-term fp16 out GEMM (pipelined) ============
// grid (16 l, 16 bh, 2 s-halves), 256 thr, CTA 128(l) x 64(d), 32 chunks of 32 s
#define LDA3 136
#define LDV3 72
#define PBUF (32 * LDA3)
#define VBUF (32 * LDV3)
__global__ __launch_bounds__(256) void out_mma_kernel(const float* __restrict__ values) {
    int bh = blockIdx.y;
    int b  = bh >> 3, h = bh & 7;
    int lbase = blockIdx.x * 128;
    int zhalf = blockIdx.z;

    __shared__ __align__(16) char smemraw[33280];
    __half* Pf0 = (__half*)smemraw;                  // [2][PBUF]
    __half* Vh0 = Pf0 + 2 * PBUF;                    // [2][VBUF]
    float* osb = (float*)smemraw;                    // [128][65] after loop

    int tid = threadIdx.x;
    int lane = tid & 31, wid = tid >> 5;
    int g = lane >> 2, tg = lane & 3;
    int mat = lane >> 3, mr = lane & 7;
    int wm = wid >> 1, wn = wid & 1;

    float4 acc[2][4];
#pragma unroll
    for (int i = 0; i < 2; i++)
#pragma unroll
        for (int j = 0; j < 4; j++) acc[i][j] = make_float4(0.f, 0.f, 0.f, 0.f);

    const size_t Pb = (size_t)bh * L_ * L_;
    const float* vptr = values + (size_t)b * L_ * E_ + h * D_;
    const float* Ebase = &g_E[((size_t)blockIdx.x * BH + bh) * L_];

    int psc0 = tid >> 4, pc8_0 = (tid & 15) * 8;
    int vsc = tid >> 3, vdq = tid & 7;

    // ---- prologue: chunk 0 ----
    {
        int sbase = zhalf * 1024;
#pragma unroll
        for (int it = 0; it < 2; it++) {
            int sc = psc0 + it * 16;
            cp16g(&Pf0[sc * LDA3 + pc8_0], &g_Pf[Pb + (size_t)(sbase + sc) * L_ + lbase + pc8_0]);
        }
        cp_commit();
        float iz = g_invZ[bh * L_ + sbase + vsc] * __expf(Ebase[sbase + vsc]);
#pragma unroll
        for (int j = 0; j < 2; j++) {
            int d4 = vdq + 8 * j;
            float4 v4 = *(const float4*)&vptr[(size_t)(sbase + vsc) * E_ + d4 * 4];
            *(uint2*)&Vh0[vsc * LDV3 + d4 * 4] =
                make_uint2(pack_h2(v4.x * iz, v4.y * iz), pack_h2(v4.z * iz, v4.w * iz));
        }
    }

    for (int sch = 0; sch < 32; sch++) {
        int buf = sch & 1;
        float4 vr[2];
        float vizn = 0.f;
        if (sch < 31) {
            int nb = (sch + 1) & 1;
            int nsb = zhalf * 1024 + (sch + 1) * 32;
#pragma unroll
            for (int it = 0; it < 2; it++) {
                int sc = psc0 + it * 16;
                cp16g(&Pf0[nb * PBUF + sc * LDA3 + pc8_0],
                      &g_Pf[Pb + (size_t)(nsb + sc) * L_ + lbase + pc8_0]);
            }
            cp_commit();
            vizn = g_invZ[bh * L_ + nsb + vsc] * __expf(Ebase[nsb + vsc]);
            vr[0] = *(const float4*)&vptr[(size_t)(nsb + vsc) * E_ + vdq * 4];
            vr[1] = *(const float4*)&vptr[(size_t)(nsb + vsc) * E_ + vdq * 4 + 32];
            cp_wait<1>();
        } else {
            cp_wait<0>();
        }
        __syncthreads();

        const __half* Pf = Pf0 + buf * PBUF;
        const __half* Vh = Vh0 + buf * VBUF;

#pragma unroll
        for (int ks = 0; ks < 2; ks++) {
            int kofs = ks * 16;
            uint ap[2][4], vv[4][2];
            {
                int row = kofs + (mat >> 1) * 8 + mr;
#pragma unroll
                for (int mi = 0; mi < 2; mi++) {
                    int col = wm * 32 + mi * 16 + (mat & 1) * 8;
                    ldsm_x4_t(ap[mi][0], ap[mi][1], ap[mi][2], ap[mi][3], &Pf[row * LDA3 + col]);
                }
            }
            {
                int row = kofs + (mat & 1) * 8 + mr;
#pragma unroll
                for (int nj = 0; nj < 2; nj++) {
                    int col = wn * 32 + nj * 16 + (mat >> 1) * 8;
                    ldsm_x4_t(vv[2 * nj][0], vv[2 * nj][1], vv[2 * nj + 1][0], vv[2 * nj + 1][1],
                              &Vh[row * LDV3 + col]);
                }
            }
#pragma unroll
            for (int mi = 0; mi < 2; mi++)
#pragma unroll
                for (int ni = 0; ni < 4; ni++)
                    mma_fp16(acc[mi][ni], ap[mi][0], ap[mi][1], ap[mi][2], ap[mi][3],
                             vv[ni][0], vv[ni][1]);
        }

        if (sch < 31) {   // STS prefetched scaled V into alternate buffer
            int nb = (sch + 1) & 1;
#pragma unroll
            for (int j = 0; j < 2; j++) {
                int d4 = vdq + 8 * j;
                float4 v4 = vr[j];
                *(uint2*)&Vh0[nb * VBUF + vsc * LDV3 + d4 * 4] =
                    make_uint2(pack_h2(v4.x * vizn, v4.y * vizn),
                               pack_h2(v4.z * vizn, v4.w * vizn));
            }
        }
        __syncthreads();
    }

    // accums -> osb[l][65]
#pragma unroll
    for (int mi = 0; mi < 2; mi++) {
        int l0 = wm * 32 + mi * 16 + g;
#pragma unroll
        for (int ni = 0; ni < 4; ni++) {
            int d0 = wn * 32 + ni * 8 + 2 * tg;
            float4 c = acc[mi][ni];
            osb[l0 * 65 + d0]           = c.x;
            osb[l0 * 65 + d0 + 1]       = c.y;
            osb[(l0 + 8) * 65 + d0]     = c.z;
            osb[(l0 + 8) * 65 + d0 + 1] = c.w;
        }
    }
    __syncthreads();
    {
        int dq = tid >> 2, lq = tid & 3;
        float* op = &g_Opart[(((size_t)zhalf * BH + bh) * D_ + dq) * L_ + lbase];
#pragma unroll
        for (int j = 0; j < 8; j++) {
            int l4 = lq + 4 * j;
            float4 w;
            w.x = osb[(l4 * 4 + 0) * 65 + dq];
            w.y = osb[(l4 * 4 + 1) * 65 + dq];
            w.z = osb[(l4 * 4 + 2) * 65 + dq];
            w.w = osb[(l4 * 4 + 3) * 65 + dq];
            *(float4*)&op[l4 * 4] = w;
        }
    }
}

// ============ K3b: reduce partials + faithful scatter ============
__global__ void reduce_kernel(float* __restrict__ out) {
    int idx = blockIdx.x * blockDim.x + threadIdx.x;
    if (idx >= BH * D_ * L_) return;
    int l  = idx & (L_ - 1);
    int dd = (idx >> 11) & (D_ - 1);
    int bh = idx >> 17;
    int b  = bh >> 3, h = bh & 7;
    float v = g_Opart[idx] + g_Opart[BH * D_ * L_ + idx];
    int row = dd * 32 + h * 4 + (l >> 9);
    out[((size_t)b * 2048 + row) * 512 + (l & 511)] = v;
}

// ============ launch ============
extern "C" void kernel_launch(void* const* d_in, const int* in_sizes, int n_in,
                              void* d_out, int out_size) {
    (void)in_sizes; (void)n_in; (void)out_size;
    const float* q = (const float*)d_in[0];
    const float* k = (const float*)d_in[1];
    const float* v = (const float*)d_in[2];
    float* out = (float*)d_out;

    btsplit_kernel<<<(L_ * KPZ + 255) / 256, 256>>>();
    coeff_kernel<<<B_ * L_, 288>>>(q, k);
    csplit_kernel<<<(int)(((size_t)BH * L_ * KPZ + 255) / 256), 256>>>();
    z_mma_kernel<<<dim3(16, 16, BH), 256>>>();
    zcombine_kernel<<<(BH * L_ + 255) / 256, 256>>>();
    out_mma_kernel<<<dim3(16, BH, 2), 256>>>(v);
    reduce_kernel<<<(BH * D_ * L_ + 255) / 256, 256>>>(out);
}

// round 14
// speedup vs baseline: 2.4361x; 1.1125x over previous
#include <cuda_runtime.h>
#include <cuda_fp16.h>

#define B_  2
#define L_  2048
#define E_  512
#define H_  8
#define D_  64
#define NC  65
#define KPZ 80         // fp16 K for corr GEMM: [C 65 | pad 15]
#define BH  (B_*H_)

typedef unsigned int uint;

// -------- scratch --------
__device__ __half gCz[(size_t)BH * L_ * KPZ];           // 5.2 MB [bh*L+s][80]
__device__ __half gBz[L_ * KPZ];                        // 0.33 MB [t][80]
__device__ float g_Zp[16 * BH * L_];                    // partial sums (tile-normed)
__device__ float g_E[16 * BH * L_];                     // per (ttile,row) max
__device__ float g_W[16 * BH * L_];                     // e^E * invZ
__device__ __half g_Pf[(size_t)BH * L_ * L_];           // 134 MB [bh][s][t], exp(c-m)
__device__ float g_Opart[2 * BH * D_ * L_];             // 16 MB  [z][bh][d][l]

// ---------------- helpers ----------------
__device__ __forceinline__ uint smem_u32(const void* p) {
    uint a;
    asm("{ .reg .u64 t; cvta.to.shared.u64 t, %1; cvt.u32.u64 %0, t; }" : "=r"(a) : "l"(p));
    return a;
}
__device__ __forceinline__ void mma_fp16(float4& c,
                                         uint a0, uint a1, uint a2, uint a3,
                                         uint b0, uint b1) {
    asm volatile(
        "mma.sync.aligned.m16n8k16.row.col.f32.f16.f16.f32 "
        "{%0,%1,%2,%3}, {%4,%5,%6,%7}, {%8,%9}, {%0,%1,%2,%3};"
        : "+f"(c.x), "+f"(c.y), "+f"(c.z), "+f"(c.w)
        : "r"(a0), "r"(a1), "r"(a2), "r"(a3), "r"(b0), "r"(b1));
}
__device__ __forceinline__ void ldsm_x4(uint& r0, uint& r1, uint& r2, uint& r3,
                                        const void* p) {
    uint a = smem_u32(p);
    asm volatile("ldmatrix.sync.aligned.m8n8.x4.shared.b16 {%0,%1,%2,%3}, [%4];"
                 : "=r"(r0), "=r"(r1), "=r"(r2), "=r"(r3) : "r"(a));
}
__device__ __forceinline__ void ldsm_x4_t(uint& r0, uint& r1, uint& r2, uint& r3,
                                          const void* p) {
    uint a = smem_u32(p);
    asm volatile("ldmatrix.sync.aligned.m8n8.x4.trans.shared.b16 {%0,%1,%2,%3}, [%4];"
                 : "=r"(r0), "=r"(r1), "=r"(r2), "=r"(r3) : "r"(a));
}
__device__ __forceinline__ uint pack_h2(float x, float y) {
    __half2 h = __floats2half2_rn(x, y);
    return *(uint*)&h;
}
__device__ __forceinline__ void cp16g(void* smem, const void* gmem) {
    uint a = smem_u32(smem);
    asm volatile("cp.async.cg.shared.global [%0], [%1], 16;" :: "r"(a), "l"(gmem));
}
__device__ __forceinline__ void cp_commit() { asm volatile("cp.async.commit_group;"); }
template <int N> __device__ __forceinline__ void cp_wait() {
    asm volatile("cp.async.wait_group %0;" :: "n"(N));
}

// ============ K0: fp16 basis gBz[t][80] ============
__global__ void btsplit_kernel() {
    int idx = blockIdx.x * blockDim.x + threadIdx.x;
    if (idx >= L_ * KPZ) return;
    int k = idx % KPZ, t = idx / KPZ;
    float v = 0.f;
    if (k == 0) v = 1.0f;
    else if (k < NC) {
        int f = (k + 1) >> 1;
        int ph = (f * t) & (L_ - 1);
        float s, c;
        sincospif((float)ph * (1.0f / 1024.0f), &s, &c);
        v = (k & 1) ? c : s;
    }
    gBz[idx] = __float2half(v);
}

// ============ K1: 64-pt DFTs -> fp16 coeffs (direct), head-mean subtracted ====
__global__ __launch_bounds__(288) void coeff_kernel(const float* __restrict__ q,
                                                    const float* __restrict__ kin) {
    int bs = blockIdx.x;
    int b  = bs >> 11;
    int s  = bs & (L_ - 1);

    __shared__ float sq[E_], sk[E_];
    __shared__ float twc[64], tws[64];
    __shared__ float A[H_][NC];

    int tid = threadIdx.x;
    for (int i = tid; i < E_; i += blockDim.x) {
        sq[i] = q[(size_t)bs * E_ + i];
        sk[i] = kin[(size_t)bs * E_ + i];
    }
    if (tid < 64) {
        float ss, cc;
        sincospif((float)tid * (1.0f / 32.0f), &ss, &cc);
        twc[tid] = cc; tws[tid] = ss;
    }
    __syncthreads();

    if (tid < H_ * 33) {
        int h = tid / 33, f = tid % 33;
        const float* qh = sq + h * D_;
        const float* kh = sk + h * D_;
        float Qr = 0.f, Qi = 0.f, Kr = 0.f, Ki = 0.f;
#pragma unroll 8
        for (int j = 0; j < 64; j++) {
            int m = (f * j) & 63;
            float c = twc[m], sn = tws[m];
            float qq = qh[j], kk2 = kh[j];
            Qr = fmaf(qq, c, Qr);  Qi = fmaf(-qq, sn, Qi);
            Kr = fmaf(kk2, c, Kr); Ki = fmaf(-kk2, sn, Ki);
        }
        float Xr = Qr * Kr + Qi * Ki;
        float Xi = Qi * Kr - Qr * Ki;
        if (f == 0) {
            A[h][0] = Xr * (1.0f / 2048.0f);
        } else {
            A[h][2 * f - 1] =  Xr * (1.0f / 1024.0f);
            A[h][2 * f]     = -Xi * (1.0f / 1024.0f);
        }
    }
    __syncthreads();

    // head-mean subtract + direct fp16 store (with zero padding to KPZ)
    for (int idx = tid; idx < H_ * KPZ; idx += blockDim.x) {
        int h = idx / KPZ, kk = idx % KPZ;
        float val = 0.f;
        if (kk < NC) {
            float m = 0.f;
#pragma unroll
            for (int hh = 0; hh < H_; hh++) m += A[hh][kk];
            val = A[h][kk] - m * (1.0f / H_);
        }
        gCz[((size_t)(b * H_ + h) * L_ + s) * KPZ + kk] = __float2half(val);
    }
}

// ============ K2: fp16 mma corr GEMM + tile-softmax -> fp16 P, E, Zp ========
// grid (16 t, 16 s, 16 bh), 256 thr, CTA 128x128, single K chunk of 80.
#define PCHZ 88
__global__ __launch_bounds__(256) void z_mma_kernel() {
    int bh    = blockIdx.z;
    int sbase = blockIdx.y * 128;
    int tbase = blockIdx.x * 128;

    __shared__ __align__(16) __half As[128 * PCHZ];    // 22.5 KB [s][k]
    __shared__ __align__(16) __half Bts[128 * PCHZ];   // 22.5 KB [t][k]
    __shared__ float rmx[128][5];
    __shared__ float zsh2[128][5];

    int tid = threadIdx.x;
    int lane = tid & 31, wid = tid >> 5;
    int g = lane >> 2, tg = lane & 3;
    int mat = lane >> 3, mr = lane & 7;
    int wm = wid >> 2, wn = wid & 3;        // warp tile m64 n32

    float4 acc[4][4];
#pragma unroll
    for (int i = 0; i < 4; i++)
#pragma unroll
        for (int j = 0; j < 4; j++) acc[i][j] = make_float4(0.f, 0.f, 0.f, 0.f);

    int srow = tid >> 1, spart = tid & 1;
    const __half* aG = gCz + ((size_t)bh * L_ + sbase + srow) * KPZ;
    const __half* bG = gBz + (size_t)(tbase + srow) * KPZ;

#pragma unroll
    for (int j = 0; j < 5; j++) {
        int q = spart * 5 + j;
        cp16g(As + srow * PCHZ + q * 8, aG + q * 8);
        cp16g(Bts + srow * PCHZ + q * 8, bG + q * 8);
    }
    cp_commit();
    cp_wait<0>();
    __syncthreads();

#pragma unroll
    for (int ks = 0; ks < 5; ks++) {
        int kofs = ks * 16;
        uint a[4][4], bb[4][2];
#pragma unroll
        for (int mi = 0; mi < 4; mi++) {
            int row = wm * 64 + mi * 16 + (mat & 1) * 8 + mr;
            int col = kofs + (mat >> 1) * 8;
            ldsm_x4(a[mi][0], a[mi][1], a[mi][2], a[mi][3], &As[row * PCHZ + col]);
        }
#pragma unroll
        for (int nj = 0; nj < 2; nj++) {
            int row = wn * 32 + nj * 16 + (mat >> 1) * 8 + mr;
            int col = kofs + (mat & 1) * 8;
            ldsm_x4(bb[2 * nj][0], bb[2 * nj][1], bb[2 * nj + 1][0], bb[2 * nj + 1][1],
                    &Bts[row * PCHZ + col]);
        }
#pragma unroll
        for (int mi = 0; mi < 4; mi++)
#pragma unroll
            for (int ni = 0; ni < 4; ni++)
                mma_fp16(acc[mi][ni], a[mi][0], a[mi][1], a[mi][2], a[mi][3],
                         bb[ni][0], bb[ni][1]);
    }

    // ---- epilogue: per-(row,tile) max -> exp2(c*log2e - mk) fp16 + Zp + E ----
#pragma unroll
    for (int mi = 0; mi < 4; mi++) {
        float m0 = -1e30f, m1 = -1e30f;
#pragma unroll
        for (int ni = 0; ni < 4; ni++) {
            float4 c = acc[mi][ni];
            m0 = fmaxf(m0, fmaxf(c.x, c.y));
            m1 = fmaxf(m1, fmaxf(c.z, c.w));
        }
        m0 = fmaxf(m0, __shfl_xor_sync(0xffffffffu, m0, 1));
        m0 = fmaxf(m0, __shfl_xor_sync(0xffffffffu, m0, 2));
        m1 = fmaxf(m1, __shfl_xor_sync(0xffffffffu, m1, 1));
        m1 = fmaxf(m1, __shfl_xor_sync(0xffffffffu, m1, 2));
        if (tg == 0) {
            rmx[wm * 64 + mi * 16 + g][wn]     = m0;
            rmx[wm * 64 + mi * 16 + g + 8][wn] = m1;
        }
    }
    __syncthreads();
    if (tid < 128) {
        float mm = fmaxf(fmaxf(rmx[tid][0], rmx[tid][1]), fmaxf(rmx[tid][2], rmx[tid][3]));
        rmx[tid][4] = mm;
        g_E[((size_t)blockIdx.x * BH + bh) * L_ + sbase + tid] = mm;
    }
    __syncthreads();

    const float LOG2E = 1.4426950408889634f;
    const size_t Pb = (size_t)bh * L_ * L_;
    float zl[4][2];
#pragma unroll
    for (int mi = 0; mi < 4; mi++) { zl[mi][0] = 0.f; zl[mi][1] = 0.f; }
#pragma unroll
    for (int mi = 0; mi < 4; mi++) {
        int lr0 = wm * 64 + mi * 16 + g;
        float mkA = rmx[lr0][4] * LOG2E, mkB = rmx[lr0 + 8][4] * LOG2E;
        int r0 = sbase + lr0;
#pragma unroll
        for (int ni = 0; ni < 4; ni++) {
            int tc = tbase + wn * 32 + ni * 8 + 2 * tg;
            float4 c = acc[mi][ni];
            float e0 = exp2f(fmaf(c.x, LOG2E, -mkA));
            float e1 = exp2f(fmaf(c.y, LOG2E, -mkA));
            float e2 = exp2f(fmaf(c.z, LOG2E, -mkB));
            float e3 = exp2f(fmaf(c.w, LOG2E, -mkB));
            zl[mi][0] += e0 + e1;
            zl[mi][1] += e2 + e3;
            *(uint*)&g_Pf[Pb + (size_t)r0 * L_ + tc]       = pack_h2(e0, e1);
            *(uint*)&g_Pf[Pb + (size_t)(r0 + 8) * L_ + tc] = pack_h2(e2, e3);
        }
    }
    // race-free rowsum: each (row, wn) written exactly once
#pragma unroll
    for (int mi = 0; mi < 4; mi++)
#pragma unroll
        for (int hh = 0; hh < 2; hh++) {
            float v = zl[mi][hh];
            v += __shfl_xor_sync(0xffffffffu, v, 1);
            v += __shfl_xor_sync(0xffffffffu, v, 2);
            if (tg == 0) zsh2[wm * 64 + mi * 16 + g + hh * 8][wn] = v;
        }
    __syncthreads();
    if (tid < 128)
        g_Zp[((size_t)blockIdx.x * BH + bh) * L_ + sbase + tid] =
            (zsh2[tid][0] + zsh2[tid][1]) + (zsh2[tid][2] + zsh2[tid][3]);
}

// ============ K2b: Z = sum_tt e^E * Zp -> W[tt] = e^E / Z ============
__global__ void zcombine_kernel() {
    int i = blockIdx.x * blockDim.x + threadIdx.x;
    if (i >= BH * L_) return;
    float ee[16];
    float z = 0.f;
#pragma unroll
    for (int tt = 0; tt < 16; tt++) {
        ee[tt] = __expf(g_E[(size_t)tt * (BH * L_) + i]);
        z += ee[tt] * g_Zp[(size_t)tt * (BH * L_) + i];
    }
    float iz = 1.0f / z;
#pragma unroll
    for (int tt = 0; tt < 16; tt++)
        g_W[(size_t)tt * (BH * L_) + i] = ee[tt] * iz;
}

// ============ K3: single-term fp16 out GEMM (pipelined) ============
// grid (16 l, 16 bh, 2 s-halves), 256 thr, CTA 128(l) x 64(d), 32 chunks of 32 s
#define LDA3 136
#define LDV3 72
#define PBUF (32 * LDA3)
#define VBUF (32 * LDV3)
__global__ __launch_bounds__(256) void out_mma_kernel(const float* __restrict__ values) {
    int bh = blockIdx.y;
    int b  = bh >> 3, h = bh & 7;
    int lbase = blockIdx.x * 128;
    int zhalf = blockIdx.z;

    __shared__ __align__(16) char smemraw[33280];
    __half* Pf0 = (__half*)smemraw;                  // [2][PBUF]
    __half* Vh0 = Pf0 + 2 * PBUF;                    // [2][VBUF]
    float* osb = (float*)smemraw;                    // [128][65] after loop

    int tid = threadIdx.x;
    int lane = tid & 31, wid = tid >> 5;
    int g = lane >> 2, tg = lane & 3;
    int mat = lane >> 3, mr = lane & 7;
    int wm = wid >> 1, wn = wid & 1;

    float4 acc[2][4];
#pragma unroll
    for (int i = 0; i < 2; i++)
#pragma unroll
        for (int j = 0; j < 4; j++) acc[i][j] = make_float4(0.f, 0.f, 0.f, 0.f);

    const size_t Pb = (size_t)bh * L_ * L_;
    const float* vptr = values + (size_t)b * L_ * E_ + h * D_;
    const float* Wbase = &g_W[((size_t)blockIdx.x * BH + bh) * L_];

    int psc0 = tid >> 4, pc8_0 = (tid & 15) * 8;
    int vsc = tid >> 3, vdq = tid & 7;

    // ---- prologue: chunk 0 ----
    {
        int sbase = zhalf * 1024;
#pragma unroll
        for (int it = 0; it < 2; it++) {
            int sc = psc0 + it * 16;
            cp16g(&Pf0[sc * LDA3 + pc8_0], &g_Pf[Pb + (size_t)(sbase + sc) * L_ + lbase + pc8_0]);
        }
        cp_commit();
        float iz = Wbase[sbase + vsc];
#pragma unroll
        for (int j = 0; j < 2; j++) {
            int d4 = vdq + 8 * j;
            float4 v4 = *(const float4*)&vptr[(size_t)(sbase + vsc) * E_ + d4 * 4];
            *(uint2*)&Vh0[vsc * LDV3 + d4 * 4] =
                make_uint2(pack_h2(v4.x * iz, v4.y * iz), pack_h2(v4.z * iz, v4.w * iz));
        }
    }

    for (int sch = 0; sch < 32; sch++) {
        int buf = sch & 1;
        float4 vr[2];
        float vizn = 0.f;
        if (sch < 31) {
            int nb = (sch + 1) & 1;
            int nsb = zhalf * 1024 + (sch + 1) * 32;
#pragma unroll
            for (int it = 0; it < 2; it++) {
                int sc = psc0 + it * 16;
                cp16g(&Pf0[nb * PBUF + sc * LDA3 + pc8_0],
                      &g_Pf[Pb + (size_t)(nsb + sc) * L_ + lbase + pc8_0]);
            }
            cp_commit();
            vizn = Wbase[nsb + vsc];
            vr[0] = *(const float4*)&vptr[(size_t)(nsb + vsc) * E_ + vdq * 4];
            vr[1] = *(const float4*)&vptr[(size_t)(nsb + vsc) * E_ + vdq * 4 + 32];
            cp_wait<1>();
        } else {
            cp_wait<0>();
        }
        __syncthreads();

        const __half* Pf = Pf0 + buf * PBUF;
        const __half* Vh = Vh0 + buf * VBUF;

#pragma unroll
        for (int ks = 0; ks < 2; ks++) {
            int kofs = ks * 16;
            uint ap[2][4], vv[4][2];
            {
                int row = kofs + (mat >> 1) * 8 + mr;
#pragma unroll
                for (int mi = 0; mi < 2; mi++) {
                    int col = wm * 32 + mi * 16 + (mat & 1) * 8;
                    ldsm_x4_t(ap[mi][0], ap[mi][1], ap[mi][2], ap[mi][3], &Pf[row * LDA3 + col]);
                }
            }
            {
                int row = kofs + (mat & 1) * 8 + mr;
#pragma unroll
                for (int nj = 0; nj < 2; nj++) {
                    int col = wn * 32 + nj * 16 + (mat >> 1) * 8;
                    ldsm_x4_t(vv[2 * nj][0], vv[2 * nj][1], vv[2 * nj + 1][0], vv[2 * nj + 1][1],
                              &Vh[row * LDV3 + col]);
                }
            }
#pragma unroll
            for (int mi = 0; mi < 2; mi++)
#pragma unroll
                for (int ni = 0; ni < 4; ni++)
                    mma_fp16(acc[mi][ni], ap[mi][0], ap[mi][1], ap[mi][2], ap[mi][3],
                             vv[ni][0], vv[ni][1]);
        }

        if (sch < 31) {   // STS prefetched scaled V into alternate buffer
            int nb = (sch + 1) & 1;
#pragma unroll
            for (int j = 0; j < 2; j++) {
                int d4 = vdq + 8 * j;
                float4 v4 = vr[j];
                *(uint2*)&Vh0[nb * VBUF + vsc * LDV3 + d4 * 4] =
                    make_uint2(pack_h2(v4.x * vizn, v4.y * vizn),
                               pack_h2(v4.z * vizn, v4.w * vizn));
            }
        }
        __syncthreads();
    }

    // accums -> osb[l][65]
#pragma unroll
    for (int mi = 0; mi < 2; mi++) {
        int l0 = wm * 32 + mi * 16 + g;
#pragma unroll
        for (int ni = 0; ni < 4; ni++) {
            int d0 = wn * 32 + ni * 8 + 2 * tg;
            float4 c = acc[mi][ni];
            osb[l0 * 65 + d0]           = c.x;
            osb[l0 * 65 + d0 + 1]       = c.y;
            osb[(l0 + 8) * 65 + d0]     = c.z;
            osb[(l0 + 8) * 65 + d0 + 1] = c.w;
        }
    }
    __syncthreads();
    {
        int dq = tid >> 2, lq = tid & 3;
        float* op = &g_Opart[(((size_t)zhalf * BH + bh) * D_ + dq) * L_ + lbase];
#pragma unroll
        for (int j = 0; j < 8; j++) {
            int l4 = lq + 4 * j;
            float4 w;
            w.x = osb[(l4 * 4 + 0) * 65 + dq];
            w.y = osb[(l4 * 4 + 1) * 65 + dq];
            w.z = osb[(l4 * 4 + 2) * 65 + dq];
            w.w = osb[(l4 * 4 + 3) * 65 + dq];
            *(float4*)&op[l4 * 4] = w;
        }
    }
}

// ============ K3b: reduce partials + faithful scatter ============
__global__ void reduce_kernel(float* __restrict__ out) {
    int idx = blockIdx.x * blockDim.x + threadIdx.x;
    if (idx >= BH * D_ * L_) return;
    int l  = idx & (L_ - 1);
    int dd = (idx >> 11) & (D_ - 1);
    int bh = idx >> 17;
    int b  = bh >> 3, h = bh & 7;
    float v = g_Opart[idx] + g_Opart[BH * D_ * L_ + idx];
    int row = dd * 32 + h * 4 + (l >> 9);
    out[((size_t)b * 2048 + row) * 512 + (l & 511)] = v;
}

// ============ launch ============
extern "C" void kernel_launch(void* const* d_in, const int* in_sizes, int n_in,
                              void* d_out, int out_size) {
    (void)in_sizes; (void)n_in; (void)out_size;
    const float* q = (const float*)d_in[0];
    const float* k = (const float*)d_in[1];
    const float* v = (const float*)d_in[2];
    float* out = (float*)d_out;

    btsplit_kernel<<<(L_ * KPZ + 255) / 256, 256>>>();
    coeff_kernel<<<B_ * L_, 288>>>(q, k);
    z_mma_kernel<<<dim3(16, 16, BH), 256>>>();
    zcombine_kernel<<<(BH * L_ + 255) / 256, 256>>>();
    out_mma_kernel<<<dim3(16, BH, 2), 256>>>(v);
    reduce_kernel<<<(BH * D_ * L_ + 255) / 256, 256>>>(out);
}